// round 2
// baseline (speedup 1.0000x reference)
#include <cuda_runtime.h>
#include <math.h>

#define NCB   10
#define KCB   2048
#define DD    256
#define SEMD  256
#define W2VD  1024
#define BT    16384              // B*T tokens
#define ZQ_ELEMS (BT*DD)         // 4194304
#define CODES_OFF ZQ_ELEMS
#define VQ_OFF   (CODES_OFF + BT*NCB)
#define SEM_OFF  (VQ_OFF + 1)
#define APAD  68                 // padded smem row stride (16B-aligned, conflict-free)

// -------- device scratch (no runtime allocation allowed) --------
__device__ float g_res[ZQ_ELEMS];     // residual, 16 MB
__device__ float g_H[BT*SEMD];        // semantic hidden, 16 MB
__device__ float g_en[NCB*KCB];       // ||e_k||^2 per codebook
__device__ float g_xx[BT];            // ||x||^2 per token (current residual)
__device__ int   g_idx[BT];           // argmin index per token (current codebook)
__device__ float g_vqp[NCB];          // per-codebook sum of (q-r)^2
__device__ float g_semsum;            // sum of (pred-target)^2

// ---------------- codeword norms ----------------
__global__ void k_enorm(const float* __restrict__ E) {
    int w = (blockIdx.x * blockDim.x + threadIdx.x) >> 5;
    int lane = threadIdx.x & 31;
    if (w >= NCB * KCB) return;
    const float* e = E + (size_t)w * DD;
    float s = 0.f;
    #pragma unroll
    for (int k = 0; k < 8; k++) { float v = e[lane + 32 * k]; s += v * v; }
    #pragma unroll
    for (int off = 16; off; off >>= 1) s += __shfl_down_sync(0xffffffffu, s, off);
    if (!lane) g_en[w] = s;
}

// ---------------- init: residual = z, zero accumulators + z_q region ----------------
__global__ void k_init(const float* __restrict__ z, float* __restrict__ out) {
    int i = blockIdx.x * blockDim.x + threadIdx.x;
    if (i < ZQ_ELEMS) { g_res[i] = z[i]; out[i] = 0.f; }
    if (i < NCB) g_vqp[i] = 0.f;
    if (i == NCB) g_semsum = 0.f;
}

// ---------------- ||x||^2 per token (XLA-GPU-style warp reduce order) ----------------
__global__ void k_xx() {
    int w = (blockIdx.x * blockDim.x + threadIdx.x) >> 5;
    int lane = threadIdx.x & 31;
    if (w >= BT) return;
    const float* row = g_res + (size_t)w * DD;
    float s = 0.f;
    #pragma unroll
    for (int k = 0; k < 8; k++) { float v = row[lane + 32 * k]; s += v * v; }
    #pragma unroll
    for (int off = 16; off; off >>= 1) s += __shfl_down_sync(0xffffffffu, s, off);
    if (!lane) g_xx[w] = s;
}

// ---------------- argmin GEMM: 64 tokens x (all 2048 codewords), D=256 ----------------
// block = 256 threads (16x16), micro-tile 4x4, full A tile resident in smem,
// double-buffered 16-d B chunks (one __syncthreads per chunk).
__global__ void __launch_bounds__(256, 2)
k_argmin(const float* __restrict__ E, int cb) {
    extern __shared__ float sm[];
    float* Asm = sm;                        // [256][APAD]  (d-major, token minor)
    float* Bs  = sm + 256 * APAD;           // 2 x [16][APAD]
    float* xxs = Bs + 2 * 16 * APAD;        // [64]

    const float* en = g_en + cb * KCB;
    int tid = threadIdx.x;
    int tx = tid & 15, ty = tid >> 4;
    int m0 = blockIdx.x * 64;

    // load A tile (64 tokens x 256 d), transposed into Asm[d][tok]
    const float4* Ag = reinterpret_cast<const float4*>(g_res + (size_t)m0 * DD);
    #pragma unroll
    for (int i = 0; i < 16; i++) {
        int f = tid + 256 * i;               // 4096 float4s
        int tok = f >> 6, seg = f & 63;
        float4 v = Ag[tok * 64 + seg];
        int db = seg * 4;
        Asm[(db + 0) * APAD + tok] = v.x;
        Asm[(db + 1) * APAD + tok] = v.y;
        Asm[(db + 2) * APAD + tok] = v.z;
        Asm[(db + 3) * APAD + tok] = v.w;
    }
    if (tid < 64) xxs[tid] = g_xx[m0 + tid];

    auto loadB = [&](int cc, float* buf) {
        int nt = cc >> 4, dc = cc & 15;
        int cw = tid >> 2, seg = tid & 3;
        float4 v = *reinterpret_cast<const float4*>(
            &E[(size_t)(nt * 64 + cw) * DD + dc * 16 + seg * 4]);
        int db = seg * 4;
        buf[(db + 0) * APAD + cw] = v.x;
        buf[(db + 1) * APAD + cw] = v.y;
        buf[(db + 2) * APAD + cw] = v.z;
        buf[(db + 3) * APAD + cw] = v.w;
    };

    loadB(0, Bs);
    __syncthreads();

    float mv[4]; int mi[4];
    #pragma unroll
    for (int r = 0; r < 4; r++) { mv[r] = INFINITY; mi[r] = 0; }
    float acc[4][4];
    #pragma unroll
    for (int r = 0; r < 4; r++)
        #pragma unroll
        for (int c = 0; c < 4; c++) acc[r][c] = 0.f;

    for (int cc = 0; cc < 512; cc++) {             // 32 n-tiles * 16 d-chunks
        if (cc + 1 < 512) loadB(cc + 1, Bs + ((cc + 1) & 1) * 16 * APAD);
        const float* Bp = Bs + (cc & 1) * 16 * APAD;
        int dbase = (cc & 15) * 16;
        #pragma unroll
        for (int kk = 0; kk < 16; kk++) {
            float4 av = *reinterpret_cast<const float4*>(&Asm[(dbase + kk) * APAD + ty * 4]);
            float4 bv = *reinterpret_cast<const float4*>(&Bp[kk * APAD + tx * 4]);
            float a[4] = {av.x, av.y, av.z, av.w};
            float b[4] = {bv.x, bv.y, bv.z, bv.w};
            #pragma unroll
            for (int r = 0; r < 4; r++)
                #pragma unroll
                for (int c = 0; c < 4; c++)
                    acc[r][c] = fmaf(a[r], b[c], acc[r][c]);
        }
        if ((cc & 15) == 15) {                     // n-tile complete: argmin epilogue
            int n0 = (cc >> 4) * 64;
            #pragma unroll
            for (int r = 0; r < 4; r++) {
                float xr = xxs[ty * 4 + r];
                #pragma unroll
                for (int c = 0; c < 4; c++) {
                    int k = n0 + tx * 4 + c;
                    float t = 2.0f * acc[r][c];            // exact (x2)
                    float s = (xr - t) + __ldg(&en[k]);    // jax op order
                    if (s < mv[r]) { mv[r] = s; mi[r] = k; }
                    acc[r][c] = 0.f;
                }
            }
        }
        __syncthreads();
    }

    // reduce across the 16 tx lanes sharing each token row (first-index tie break)
    #pragma unroll
    for (int off = 1; off < 16; off <<= 1) {
        #pragma unroll
        for (int r = 0; r < 4; r++) {
            float ov = __shfl_xor_sync(0xffffffffu, mv[r], off);
            int   oi = __shfl_xor_sync(0xffffffffu, mi[r], off);
            if (ov < mv[r] || (ov == mv[r] && oi < mi[r])) { mv[r] = ov; mi[r] = oi; }
        }
    }
    if (tx == 0) {
        #pragma unroll
        for (int r = 0; r < 4; r++) g_idx[m0 + ty * 4 + r] = mi[r];
    }
}

// ---------------- straight-through update + loss partial + codes ----------------
__global__ void k_update(const float* __restrict__ Ecb, int cb, float* __restrict__ out) {
    int tok = blockIdx.x, d = threadIdx.x;
    int idx = g_idx[tok];
    size_t o = (size_t)tok * DD + d;
    float r = g_res[o];
    float q = __ldg(&Ecb[(size_t)idx * DD + d]);
    float df = q - r;                 // fl(q - r)
    float zq = r + df;                // fl(r + fl(q - r))  == jax straight-through value
    out[o] += zq;                     // z_q_total accumulation (sequential, matches jax)
    g_res[o] = r - zq;                // residual update
    float s = df * df;
    __shared__ float red[8];
    int lane = d & 31, w = d >> 5;
    #pragma unroll
    for (int off = 16; off; off >>= 1) s += __shfl_xor_sync(0xffffffffu, s, off);
    if (!lane) red[w] = s;
    __syncthreads();
    if (d < 8) {
        float t = red[d];
        #pragma unroll
        for (int off = 4; off; off >>= 1) t += __shfl_xor_sync(0xffu, t, off);
        if (d == 0) atomicAdd(&g_vqp[cb], t);
    }
    if (d == 0) out[CODES_OFF + tok * NCB + cb] = (float)idx;
}

// ---------------- semantic head GEMM1: H = gelu(zq1 @ W1 + b1) ----------------
__global__ void __launch_bounds__(256, 2)
k_gemm1(const float* __restrict__ A, const float* __restrict__ W1, const float* __restrict__ b1) {
    extern __shared__ float sm[];
    float* Asm = sm;                  // [256][APAD]
    float* Bs  = sm + 256 * APAD;     // [16][APAD]
    int tid = threadIdx.x, tx = tid & 15, ty = tid >> 4;
    int m0 = blockIdx.x * 64, n0 = blockIdx.y * 64;

    const float4* Ag = reinterpret_cast<const float4*>(A + (size_t)m0 * DD);
    #pragma unroll
    for (int i = 0; i < 16; i++) {
        int f = tid + 256 * i;
        int tok = f >> 6, seg = f & 63;
        float4 v = Ag[tok * 64 + seg];
        int db = seg * 4;
        Asm[(db + 0) * APAD + tok] = v.x;
        Asm[(db + 1) * APAD + tok] = v.y;
        Asm[(db + 2) * APAD + tok] = v.z;
        Asm[(db + 3) * APAD + tok] = v.w;
    }
    __syncthreads();

    float acc[4][4];
    #pragma unroll
    for (int r = 0; r < 4; r++)
        #pragma unroll
        for (int c = 0; c < 4; c++) acc[r][c] = 0.f;

    for (int dc = 0; dc < 16; dc++) {
        int dk = tid >> 4, nseg = tid & 15;
        float4 v = *reinterpret_cast<const float4*>(&W1[(size_t)(dc * 16 + dk) * SEMD + n0 + nseg * 4]);
        *reinterpret_cast<float4*>(&Bs[dk * APAD + nseg * 4]) = v;
        __syncthreads();
        #pragma unroll
        for (int kk = 0; kk < 16; kk++) {
            float4 av = *reinterpret_cast<const float4*>(&Asm[(dc * 16 + kk) * APAD + ty * 4]);
            float4 bv = *reinterpret_cast<const float4*>(&Bs[kk * APAD + tx * 4]);
            float a[4] = {av.x, av.y, av.z, av.w};
            float b[4] = {bv.x, bv.y, bv.z, bv.w};
            #pragma unroll
            for (int r = 0; r < 4; r++)
                #pragma unroll
                for (int c = 0; c < 4; c++)
                    acc[r][c] = fmaf(a[r], b[c], acc[r][c]);
        }
        __syncthreads();
    }
    #pragma unroll
    for (int r = 0; r < 4; r++)
        #pragma unroll
        for (int c = 0; c < 4; c++) {
            int m = m0 + ty * 4 + r, n = n0 + tx * 4 + c;
            float x = acc[r][c] + __ldg(&b1[n]);
            float h = 0.5f * x * (1.0f + erff(x * 0.70710678118654752f));
            g_H[(size_t)m * SEMD + n] = h;
        }
}

// ---------------- semantic head GEMM2 + fused MSE reduction ----------------
__global__ void __launch_bounds__(256, 2)
k_gemm2(const float* __restrict__ W2, const float* __restrict__ b2, const float* __restrict__ tgt) {
    extern __shared__ float sm[];
    float* Asm = sm;
    float* Bs  = sm + 256 * APAD;
    int tid = threadIdx.x, tx = tid & 15, ty = tid >> 4;
    int m0 = blockIdx.x * 64, n0 = blockIdx.y * 64;

    const float4* Ag = reinterpret_cast<const float4*>(g_H + (size_t)m0 * SEMD);
    #pragma unroll
    for (int i = 0; i < 16; i++) {
        int f = tid + 256 * i;
        int tok = f >> 6, seg = f & 63;
        float4 v = Ag[tok * 64 + seg];
        int db = seg * 4;
        Asm[(db + 0) * APAD + tok] = v.x;
        Asm[(db + 1) * APAD + tok] = v.y;
        Asm[(db + 2) * APAD + tok] = v.z;
        Asm[(db + 3) * APAD + tok] = v.w;
    }
    __syncthreads();

    float acc[4][4];
    #pragma unroll
    for (int r = 0; r < 4; r++)
        #pragma unroll
        for (int c = 0; c < 4; c++) acc[r][c] = 0.f;

    for (int dc = 0; dc < 16; dc++) {
        int dk = tid >> 4, nseg = tid & 15;
        float4 v = *reinterpret_cast<const float4*>(&W2[(size_t)(dc * 16 + dk) * W2VD + n0 + nseg * 4]);
        *reinterpret_cast<float4*>(&Bs[dk * APAD + nseg * 4]) = v;
        __syncthreads();
        #pragma unroll
        for (int kk = 0; kk < 16; kk++) {
            float4 av = *reinterpret_cast<const float4*>(&Asm[(dc * 16 + kk) * APAD + ty * 4]);
            float4 bv = *reinterpret_cast<const float4*>(&Bs[kk * APAD + tx * 4]);
            float a[4] = {av.x, av.y, av.z, av.w};
            float b[4] = {bv.x, bv.y, bv.z, bv.w};
            #pragma unroll
            for (int r = 0; r < 4; r++)
                #pragma unroll
                for (int c = 0; c < 4; c++)
                    acc[r][c] = fmaf(a[r], b[c], acc[r][c]);
        }
        __syncthreads();
    }

    float ls = 0.f;
    #pragma unroll
    for (int r = 0; r < 4; r++)
        #pragma unroll
        for (int c = 0; c < 4; c++) {
            int m = m0 + ty * 4 + r, n = n0 + tx * 4 + c;
            float p = acc[r][c] + __ldg(&b2[n]);
            float d = p - __ldg(&tgt[(size_t)m * W2VD + n]);
            ls += d * d;
        }
    __shared__ float red[8];
    int lane = tid & 31, w = tid >> 5;
    #pragma unroll
    for (int off = 16; off; off >>= 1) ls += __shfl_xor_sync(0xffffffffu, ls, off);
    if (!lane) red[w] = ls;
    __syncthreads();
    if (tid < 8) {
        float t = red[tid];
        #pragma unroll
        for (int off = 4; off; off >>= 1) t += __shfl_xor_sync(0xffu, t, off);
        if (tid == 0) atomicAdd(&g_semsum, t);
    }
}

// ---------------- finalize scalars ----------------
__global__ void k_fin(float* __restrict__ out) {
    if (threadIdx.x == 0) {
        float vq = 0.f;
        #pragma unroll
        for (int i = 0; i < NCB; i++) {
            float m = g_vqp[i] * (1.0f / 4194304.0f);   // mean over B*T*D
            vq += m + 0.25f * m;                         // embedding + COMMIT*commitment
        }
        out[VQ_OFF] = vq;
        out[SEM_OFF] = g_semsum * (1.0f / 16777216.0f);  // mean over B*T*W2V
    }
}

// ---------------- launch ----------------
extern "C" void kernel_launch(void* const* d_in, const int* in_sizes, int n_in,
                              void* d_out, int out_size) {
    const float* z   = (const float*)d_in[0];
    const float* w2v = (const float*)d_in[1];
    const float* E   = (const float*)d_in[2];
    const float* W1  = (const float*)d_in[3];
    const float* b1  = (const float*)d_in[4];
    const float* W2  = (const float*)d_in[5];
    const float* b2  = (const float*)d_in[6];
    float* out = (float*)d_out;

    const int ARG_SMEM  = (256 * APAD + 2 * 16 * APAD + 64) * 4;   // 78592 B
    const int GEMM_SMEM = (256 * APAD + 16 * APAD) * 4;            // 73984 B
    cudaFuncSetAttribute(k_argmin, cudaFuncAttributeMaxDynamicSharedMemorySize, ARG_SMEM);
    cudaFuncSetAttribute(k_gemm1,  cudaFuncAttributeMaxDynamicSharedMemorySize, GEMM_SMEM);
    cudaFuncSetAttribute(k_gemm2,  cudaFuncAttributeMaxDynamicSharedMemorySize, GEMM_SMEM);

    k_enorm<<<(NCB * KCB * 32 + 255) / 256, 256>>>(E);
    k_init<<<(ZQ_ELEMS + 1023) / 1024, 1024>>>(z, out);

    for (int cb = 0; cb < NCB; cb++) {
        const float* Ecb = E + (size_t)cb * KCB * DD;
        k_xx<<<(BT * 32 + 255) / 256, 256>>>();
        k_argmin<<<BT / 64, 256, ARG_SMEM>>>(Ecb, cb);
        k_update<<<BT, 256>>>(Ecb, cb, out);
        if (cb == 0) {
            k_gemm1<<<dim3(BT / 64, SEMD / 64), 256, GEMM_SMEM>>>(out, W1, b1);
            k_gemm2<<<dim3(BT / 64, W2VD / 64), 256, GEMM_SMEM>>>(W2, b2, w2v);
        }
    }
    k_fin<<<1, 32>>>(out);
}

// round 3
// speedup vs baseline: 1.1669x; 1.1669x over previous
#include <cuda_runtime.h>
#include <math.h>

#define NCB   10
#define KCB   2048
#define DD    256
#define SEMD  256
#define W2VD  1024
#define BT    16384              // B*T tokens
#define ZQ_ELEMS (BT*DD)         // 4194304
#define CODES_OFF ZQ_ELEMS
#define VQ_OFF   (CODES_OFF + BT*NCB)
#define SEM_OFF  (VQ_OFF + 1)
#define APAD  68                 // A smem row stride (floats, 16B aligned)
#define BPAD  264                // B smem row stride (floats, 16B aligned)

// -------- device scratch (no runtime allocation allowed) --------
__device__ float g_res[ZQ_ELEMS];     // residual, 16 MB
__device__ float g_H[BT*SEMD];        // semantic hidden, 16 MB
__device__ float g_en[NCB*KCB];       // ||e_k||^2 per codebook
__device__ float g_xx[BT];            // ||x||^2 per token (current residual)
__device__ float g_vqp[NCB];          // per-codebook sum of (q-r)^2
__device__ float g_semsum;            // sum of (pred-target)^2

// packed fp32x2 FMA (sm_103a): two bitwise-exact IEEE fp32 FMAs per issue slot
__device__ __forceinline__ void fma2(unsigned long long& d,
                                     unsigned long long a, unsigned long long b) {
    asm("fma.rn.f32x2 %0, %1, %2, %0;" : "+l"(d) : "l"(a), "l"(b));
}
__device__ __forceinline__ unsigned long long dup2(float a) {
    unsigned long long r;
    asm("mov.b64 %0, {%1, %1};" : "=l"(r) : "f"(a));
    return r;
}
__device__ __forceinline__ void unpk(float& lo, float& hi, unsigned long long v) {
    asm("mov.b64 {%0, %1}, %2;" : "=f"(lo), "=f"(hi) : "l"(v));
}

// ---------------- codeword norms ----------------
__global__ void k_enorm(const float* __restrict__ E) {
    int w = (blockIdx.x * blockDim.x + threadIdx.x) >> 5;
    int lane = threadIdx.x & 31;
    if (w >= NCB * KCB) return;
    const float* e = E + (size_t)w * DD;
    float s = 0.f;
    #pragma unroll
    for (int k = 0; k < 8; k++) { float v = e[lane + 32 * k]; s += v * v; }
    #pragma unroll
    for (int off = 16; off; off >>= 1) s += __shfl_down_sync(0xffffffffu, s, off);
    if (!lane) g_en[w] = s;
}

// ---------------- init: residual = z, zero accumulators + z_q region ----------------
__global__ void k_init(const float* __restrict__ z, float* __restrict__ out) {
    int i = blockIdx.x * blockDim.x + threadIdx.x;
    if (i < ZQ_ELEMS) { g_res[i] = z[i]; out[i] = 0.f; }
    if (i < NCB) g_vqp[i] = 0.f;
    if (i == NCB) g_semsum = 0.f;
}

// ---------------- ||x||^2 per token (initial only; later fused) ----------------
__global__ void k_xx() {
    int w = (blockIdx.x * blockDim.x + threadIdx.x) >> 5;
    int lane = threadIdx.x & 31;
    if (w >= BT) return;
    const float* row = g_res + (size_t)w * DD;
    float s = 0.f;
    #pragma unroll
    for (int k = 0; k < 8; k++) { float v = row[lane + 32 * k]; s += v * v; }
    #pragma unroll
    for (int off = 16; off; off >>= 1) s += __shfl_down_sync(0xffffffffu, s, off);
    if (!lane) g_xx[w] = s;
}

// ---------------- fused argmin GEMM + straight-through update ----------------
// block = 256 threads = 8 warps. Warp wy owns tokens [m0+wy*8, +8).
// Thread (wy, lane): 8 tokens x 8 codewords (cw = {lane*4..+3} and {128+lane*4..+3}).
// Sweeps K=2048 in 8 n-tiles of 256 cw; d in 16 chunks of 16 per n-tile.
// Epilogue per warp: argmin reduce, then residual/z_q/xx/loss/codes update.
__global__ void __launch_bounds__(256, 2)
k_argmin(const float* __restrict__ Ecb, int cb, float* __restrict__ out) {
    extern __shared__ float sm[];
    float* Asm = sm;                        // [256 d][APAD]  (token minor)
    float* Bs  = sm + 256 * APAD;           // 2 x [16 d][BPAD] (cw minor)
    float* xxs = Bs + 2 * 16 * BPAD;        // [64]

    const float* en = g_en + cb * KCB;
    int tid = threadIdx.x;
    int lane = tid & 31, wy = tid >> 5;
    int m0 = blockIdx.x * 64;

    // load A tile (64 tokens x 256 d), transposed into Asm[d][tok]
    const float4* Ag = reinterpret_cast<const float4*>(g_res + (size_t)m0 * DD);
    #pragma unroll
    for (int i = 0; i < 16; i++) {
        int f = tid + 256 * i;               // 4096 float4s
        int tok = f >> 6, seg = f & 63;
        float4 v = Ag[tok * 64 + seg];
        int db = seg * 4;
        Asm[(db + 0) * APAD + tok] = v.x;
        Asm[(db + 1) * APAD + tok] = v.y;
        Asm[(db + 2) * APAD + tok] = v.z;
        Asm[(db + 3) * APAD + tok] = v.w;
    }
    if (tid < 64) xxs[tid] = g_xx[m0 + tid];

    const float4* E4 = reinterpret_cast<const float4*>(Ecb);
    // load one 16d x 256cw chunk of E (transposed) into buffer
    auto loadB = [&](int cc, float* buf) {
        int nt = cc >> 4, dc = cc & 15;
        int row = nt * 256 + tid;            // one codeword per thread
        #pragma unroll
        for (int j = 0; j < 4; j++) {
            float4 v = E4[(size_t)row * 64 + dc * 4 + j];
            buf[(j * 4 + 0) * BPAD + tid] = v.x;
            buf[(j * 4 + 1) * BPAD + tid] = v.y;
            buf[(j * 4 + 2) * BPAD + tid] = v.z;
            buf[(j * 4 + 3) * BPAD + tid] = v.w;
        }
    };

    loadB(0, Bs);
    __syncthreads();

    float mv[8]; int mi[8];
    #pragma unroll
    for (int r = 0; r < 8; r++) { mv[r] = INFINITY; mi[r] = 0; }
    unsigned long long acc[8][4];
    #pragma unroll
    for (int r = 0; r < 8; r++)
        #pragma unroll
        for (int q = 0; q < 4; q++) acc[r][q] = 0ull;

    for (int cc = 0; cc < 128; cc++) {             // 8 n-tiles * 16 d-chunks
        if (cc + 1 < 128) loadB(cc + 1, Bs + ((cc + 1) & 1) * 16 * BPAD);
        const float* Bp = Bs + (cc & 1) * 16 * BPAD;
        int dbase = (cc & 15) * 16;
        #pragma unroll
        for (int kk = 0; kk < 16; kk++) {
            // b: 8 codewords as 4 f32x2 (two coalesced LDS.128)
            const unsigned long long* br =
                reinterpret_cast<const unsigned long long*>(&Bp[kk * BPAD]);
            unsigned long long b0 = br[lane * 2 + 0];
            unsigned long long b1 = br[lane * 2 + 1];
            unsigned long long b2 = br[64 + lane * 2 + 0];
            unsigned long long b3 = br[64 + lane * 2 + 1];
            // a: 8 token values (broadcast LDS.128 x2)
            float4 av0 = *reinterpret_cast<const float4*>(&Asm[(dbase + kk) * APAD + wy * 8]);
            float4 av1 = *reinterpret_cast<const float4*>(&Asm[(dbase + kk) * APAD + wy * 8 + 4]);
            float a[8] = {av0.x, av0.y, av0.z, av0.w, av1.x, av1.y, av1.z, av1.w};
            #pragma unroll
            for (int r = 0; r < 8; r++) {
                unsigned long long a2 = dup2(a[r]);
                fma2(acc[r][0], a2, b0);
                fma2(acc[r][1], a2, b1);
                fma2(acc[r][2], a2, b2);
                fma2(acc[r][3], a2, b3);
            }
        }
        if ((cc & 15) == 15) {                     // n-tile complete: argmin epilogue
            int n0 = (cc >> 4) * 256;
            #pragma unroll
            for (int r = 0; r < 8; r++) {
                float xr = xxs[wy * 8 + r];
                #pragma unroll
                for (int q = 0; q < 4; q++) {
                    int kb = n0 + (q >> 1) * 128 + lane * 4 + (q & 1) * 2;
                    float lo, hi;
                    unpk(lo, hi, acc[r][q]);
                    float s0 = (xr - 2.0f * lo) + __ldg(&en[kb]);
                    float s1 = (xr - 2.0f * hi) + __ldg(&en[kb + 1]);
                    if (s0 < mv[r]) { mv[r] = s0; mi[r] = kb; }
                    if (s1 < mv[r]) { mv[r] = s1; mi[r] = kb + 1; }
                    acc[r][q] = 0ull;
                }
            }
        }
        __syncthreads();
    }

    // argmin reduce across 32 lanes (first-index tie break)
    #pragma unroll
    for (int off = 1; off < 32; off <<= 1) {
        #pragma unroll
        for (int r = 0; r < 8; r++) {
            float ov = __shfl_xor_sync(0xffffffffu, mv[r], off);
            int   oi = __shfl_xor_sync(0xffffffffu, mi[r], off);
            if (ov < mv[r] || (ov == mv[r] && oi < mi[r])) { mv[r] = ov; mi[r] = oi; }
        }
    }

    // fused straight-through update for this warp's 8 tokens
    float sl = 0.f;
    #pragma unroll
    for (int r = 0; r < 8; r++) {
        int tok = m0 + wy * 8 + r;
        int idx = mi[r];
        const float* qrow = Ecb + (size_t)idx * DD;
        float* rrow = g_res + (size_t)tok * DD;
        float* orow = out + (size_t)tok * DD;
        float sx = 0.f;
        #pragma unroll
        for (int j = 0; j < 8; j++) {
            int d = lane + 32 * j;
            float rr = rrow[d];
            float q  = __ldg(&qrow[d]);
            float df = q - rr;                 // fl(q - r)
            float zq = rr + df;                // straight-through value, jax order
            float nr = rr - zq;                // new residual
            orow[d] += zq;                     // z_q_total accumulation
            rrow[d] = nr;
            sl += df * df;
            sx += nr * nr;                     // xx for next codebook (k_xx order)
        }
        #pragma unroll
        for (int off = 16; off; off >>= 1) sx += __shfl_down_sync(0xffffffffu, sx, off);
        if (lane == 0) {
            g_xx[tok] = sx;
            out[CODES_OFF + tok * NCB + cb] = (float)idx;
        }
    }
    #pragma unroll
    for (int off = 16; off; off >>= 1) sl += __shfl_xor_sync(0xffffffffu, sl, off);
    if (lane == 0) atomicAdd(&g_vqp[cb], sl);
}

// ---------------- semantic head GEMM1: H = gelu(zq1 @ W1 + b1) ----------------
__global__ void __launch_bounds__(256, 2)
k_gemm1(const float* __restrict__ A, const float* __restrict__ W1, const float* __restrict__ b1) {
    extern __shared__ float sm[];
    float* Asm = sm;                  // [256][APAD]
    float* Bs  = sm + 256 * APAD;     // [16][APAD]
    int tid = threadIdx.x, tx = tid & 15, ty = tid >> 4;
    int m0 = blockIdx.x * 64, n0 = blockIdx.y * 64;

    const float4* Ag = reinterpret_cast<const float4*>(A + (size_t)m0 * DD);
    #pragma unroll
    for (int i = 0; i < 16; i++) {
        int f = tid + 256 * i;
        int tok = f >> 6, seg = f & 63;
        float4 v = Ag[tok * 64 + seg];
        int db = seg * 4;
        Asm[(db + 0) * APAD + tok] = v.x;
        Asm[(db + 1) * APAD + tok] = v.y;
        Asm[(db + 2) * APAD + tok] = v.z;
        Asm[(db + 3) * APAD + tok] = v.w;
    }
    __syncthreads();

    float acc[4][4];
    #pragma unroll
    for (int r = 0; r < 4; r++)
        #pragma unroll
        for (int c = 0; c < 4; c++) acc[r][c] = 0.f;

    for (int dc = 0; dc < 16; dc++) {
        int dk = tid >> 4, nseg = tid & 15;
        float4 v = *reinterpret_cast<const float4*>(&W1[(size_t)(dc * 16 + dk) * SEMD + n0 + nseg * 4]);
        *reinterpret_cast<float4*>(&Bs[dk * APAD + nseg * 4]) = v;
        __syncthreads();
        #pragma unroll
        for (int kk = 0; kk < 16; kk++) {
            float4 av = *reinterpret_cast<const float4*>(&Asm[(dc * 16 + kk) * APAD + ty * 4]);
            float4 bv = *reinterpret_cast<const float4*>(&Bs[kk * APAD + tx * 4]);
            float a[4] = {av.x, av.y, av.z, av.w};
            float b[4] = {bv.x, bv.y, bv.z, bv.w};
            #pragma unroll
            for (int r = 0; r < 4; r++)
                #pragma unroll
                for (int c = 0; c < 4; c++)
                    acc[r][c] = fmaf(a[r], b[c], acc[r][c]);
        }
        __syncthreads();
    }
    #pragma unroll
    for (int r = 0; r < 4; r++)
        #pragma unroll
        for (int c = 0; c < 4; c++) {
            int m = m0 + ty * 4 + r, n = n0 + tx * 4 + c;
            float x = acc[r][c] + __ldg(&b1[n]);
            float h = 0.5f * x * (1.0f + erff(x * 0.70710678118654752f));
            g_H[(size_t)m * SEMD + n] = h;
        }
}

// ---------------- semantic head GEMM2 + fused MSE reduction ----------------
__global__ void __launch_bounds__(256, 2)
k_gemm2(const float* __restrict__ W2, const float* __restrict__ b2, const float* __restrict__ tgt) {
    extern __shared__ float sm[];
    float* Asm = sm;
    float* Bs  = sm + 256 * APAD;
    int tid = threadIdx.x, tx = tid & 15, ty = tid >> 4;
    int m0 = blockIdx.x * 64, n0 = blockIdx.y * 64;

    const float4* Ag = reinterpret_cast<const float4*>(g_H + (size_t)m0 * SEMD);
    #pragma unroll
    for (int i = 0; i < 16; i++) {
        int f = tid + 256 * i;
        int tok = f >> 6, seg = f & 63;
        float4 v = Ag[tok * 64 + seg];
        int db = seg * 4;
        Asm[(db + 0) * APAD + tok] = v.x;
        Asm[(db + 1) * APAD + tok] = v.y;
        Asm[(db + 2) * APAD + tok] = v.z;
        Asm[(db + 3) * APAD + tok] = v.w;
    }
    __syncthreads();

    float acc[4][4];
    #pragma unroll
    for (int r = 0; r < 4; r++)
        #pragma unroll
        for (int c = 0; c < 4; c++) acc[r][c] = 0.f;

    for (int dc = 0; dc < 16; dc++) {
        int dk = tid >> 4, nseg = tid & 15;
        float4 v = *reinterpret_cast<const float4*>(&W2[(size_t)(dc * 16 + dk) * W2VD + n0 + nseg * 4]);
        *reinterpret_cast<float4*>(&Bs[dk * APAD + nseg * 4]) = v;
        __syncthreads();
        #pragma unroll
        for (int kk = 0; kk < 16; kk++) {
            float4 av = *reinterpret_cast<const float4*>(&Asm[(dc * 16 + kk) * APAD + ty * 4]);
            float4 bv = *reinterpret_cast<const float4*>(&Bs[kk * APAD + tx * 4]);
            float a[4] = {av.x, av.y, av.z, av.w};
            float b[4] = {bv.x, bv.y, bv.z, bv.w};
            #pragma unroll
            for (int r = 0; r < 4; r++)
                #pragma unroll
                for (int c = 0; c < 4; c++)
                    acc[r][c] = fmaf(a[r], b[c], acc[r][c]);
        }
        __syncthreads();
    }

    float ls = 0.f;
    #pragma unroll
    for (int r = 0; r < 4; r++)
        #pragma unroll
        for (int c = 0; c < 4; c++) {
            int m = m0 + ty * 4 + r, n = n0 + tx * 4 + c;
            float p = acc[r][c] + __ldg(&b2[n]);
            float d = p - __ldg(&tgt[(size_t)m * W2VD + n]);
            ls += d * d;
        }
    __shared__ float red[8];
    int lane = tid & 31, w = tid >> 5;
    #pragma unroll
    for (int off = 16; off; off >>= 1) ls += __shfl_xor_sync(0xffffffffu, ls, off);
    if (!lane) red[w] = ls;
    __syncthreads();
    if (tid < 8) {
        float t = red[tid];
        #pragma unroll
        for (int off = 4; off; off >>= 1) t += __shfl_xor_sync(0xffu, t, off);
        if (tid == 0) atomicAdd(&g_semsum, t);
    }
}

// ---------------- finalize scalars ----------------
__global__ void k_fin(float* __restrict__ out) {
    if (threadIdx.x == 0) {
        float vq = 0.f;
        #pragma unroll
        for (int i = 0; i < NCB; i++) {
            float m = g_vqp[i] * (1.0f / 4194304.0f);   // mean over B*T*D
            vq += m + 0.25f * m;                         // embedding + COMMIT*commitment
        }
        out[VQ_OFF] = vq;
        out[SEM_OFF] = g_semsum * (1.0f / 16777216.0f);  // mean over B*T*W2V
    }
}

// ---------------- launch ----------------
extern "C" void kernel_launch(void* const* d_in, const int* in_sizes, int n_in,
                              void* d_out, int out_size) {
    const float* z   = (const float*)d_in[0];
    const float* w2v = (const float*)d_in[1];
    const float* E   = (const float*)d_in[2];
    const float* W1  = (const float*)d_in[3];
    const float* b1  = (const float*)d_in[4];
    const float* W2  = (const float*)d_in[5];
    const float* b2  = (const float*)d_in[6];
    float* out = (float*)d_out;

    const int ARG_SMEM  = (256 * APAD + 2 * 16 * BPAD + 64) * 4;   // 103,680 B
    const int GEMM_SMEM = (256 * APAD + 16 * APAD) * 4;            // 73,984 B
    cudaFuncSetAttribute(k_argmin, cudaFuncAttributeMaxDynamicSharedMemorySize, ARG_SMEM);
    cudaFuncSetAttribute(k_gemm1,  cudaFuncAttributeMaxDynamicSharedMemorySize, GEMM_SMEM);
    cudaFuncSetAttribute(k_gemm2,  cudaFuncAttributeMaxDynamicSharedMemorySize, GEMM_SMEM);

    k_enorm<<<(NCB * KCB * 32 + 255) / 256, 256>>>(E);
    k_init<<<(ZQ_ELEMS + 1023) / 1024, 1024>>>(z, out);
    k_xx<<<(BT * 32 + 255) / 256, 256>>>();

    for (int cb = 0; cb < NCB; cb++) {
        const float* Ecb = E + (size_t)cb * KCB * DD;
        k_argmin<<<BT / 64, 256, ARG_SMEM>>>(Ecb, cb, out);
        if (cb == 0) {
            k_gemm1<<<dim3(BT / 64, SEMD / 64), 256, GEMM_SMEM>>>(out, W1, b1);
            k_gemm2<<<dim3(BT / 64, W2VD / 64), 256, GEMM_SMEM>>>(W2, b2, w2v);
        }
    }
    k_fin<<<1, 32>>>(out);
}

// round 4
// speedup vs baseline: 1.3899x; 1.1911x over previous
#include <cuda_runtime.h>
#include <math.h>

#define NCB   10
#define KCB   2048
#define DD    256
#define SEMD  256
#define W2VD  1024
#define BT    16384              // B*T tokens
#define ZQ_ELEMS (BT*DD)         // 4194304
#define CODES_OFF ZQ_ELEMS
#define VQ_OFF   (CODES_OFF + BT*NCB)
#define SEM_OFF  (VQ_OFF + 1)
#define APAD  68                 // A smem row stride (floats, 16B aligned)
#define BPAD  264                // B smem row stride (floats, 16B aligned)

// -------- device scratch (no runtime allocation allowed) --------
__device__ float g_res[ZQ_ELEMS];     // residual, 16 MB
__device__ float g_H[BT*SEMD];        // semantic hidden, 16 MB
__device__ float g_en[NCB*KCB];       // ||e_k||^2 per codebook
__device__ float g_xx[BT];            // ||x||^2 per token (current residual)
__device__ float g_vqp[NCB];          // per-codebook sum of (q-r)^2
__device__ float g_semsum;            // sum of (pred-target)^2

// packed fp32x2 FMA (sm_103a): two bitwise-exact IEEE fp32 FMAs per issue slot
__device__ __forceinline__ void fma2(unsigned long long& d,
                                     unsigned long long a, unsigned long long b) {
    asm("fma.rn.f32x2 %0, %1, %2, %0;" : "+l"(d) : "l"(a), "l"(b));
}
__device__ __forceinline__ unsigned long long dup2(float a) {
    unsigned long long r;
    asm("mov.b64 %0, {%1, %1};" : "=l"(r) : "f"(a));
    return r;
}
__device__ __forceinline__ void unpk(float& lo, float& hi, unsigned long long v) {
    asm("mov.b64 {%0, %1}, %2;" : "=f"(lo), "=f"(hi) : "l"(v));
}

// ---------------- codeword norms ----------------
__global__ void k_enorm(const float* __restrict__ E) {
    int w = (blockIdx.x * blockDim.x + threadIdx.x) >> 5;
    int lane = threadIdx.x & 31;
    if (w >= NCB * KCB) return;
    const float* e = E + (size_t)w * DD;
    float s = 0.f;
    #pragma unroll
    for (int k = 0; k < 8; k++) { float v = e[lane + 32 * k]; s += v * v; }
    #pragma unroll
    for (int off = 16; off; off >>= 1) s += __shfl_down_sync(0xffffffffu, s, off);
    if (!lane) g_en[w] = s;
}

// ---------------- init: residual = z, zero accumulators + z_q region ----------------
__global__ void k_init(const float* __restrict__ z, float* __restrict__ out) {
    int i = blockIdx.x * blockDim.x + threadIdx.x;
    if (i < ZQ_ELEMS) { g_res[i] = z[i]; out[i] = 0.f; }
    if (i < NCB) g_vqp[i] = 0.f;
    if (i == NCB) g_semsum = 0.f;
}

// ---------------- ||x||^2 per token (initial only; later fused) ----------------
__global__ void k_xx() {
    int w = (blockIdx.x * blockDim.x + threadIdx.x) >> 5;
    int lane = threadIdx.x & 31;
    if (w >= BT) return;
    const float* row = g_res + (size_t)w * DD;
    float s = 0.f;
    #pragma unroll
    for (int k = 0; k < 8; k++) { float v = row[lane + 32 * k]; s += v * v; }
    #pragma unroll
    for (int off = 16; off; off >>= 1) s += __shfl_down_sync(0xffffffffu, s, off);
    if (!lane) g_xx[w] = s;
}

// ---------------- fused argmin GEMM + straight-through update ----------------
// block = 256 threads = 8 warps. Warp wy owns tokens [m0+wy*8, +8).
// Thread (wy, lane): 8 tokens x 8 codewords. K swept in 8 n-tiles of 256 cw;
// d in 16 chunks of 16 per n-tile. B chunk software-pipelined: LDG->regs at cc
// start, STS into the idle double-buffer after the compute has covered latency.
__global__ void __launch_bounds__(256, 2)
k_argmin(const float* __restrict__ Ecb, int cb, float* __restrict__ out) {
    extern __shared__ float sm[];
    float* Asm = sm;                        // [256 d][APAD]  (token minor)
    float* Bs  = sm + 256 * APAD;           // 2 x [16 d][BPAD] (cw minor)
    float* xxs = Bs + 2 * 16 * BPAD;        // [64]
    float* ens = xxs + 64;                  // [2048] codeword norms

    int tid = threadIdx.x;
    int lane = tid & 31, wy = tid >> 5;
    int m0 = blockIdx.x * 64;

    // stage codeword norms for this codebook into smem (2048 floats)
    {
        const float4* en4 = reinterpret_cast<const float4*>(g_en + cb * KCB);
        float4 v0 = en4[tid * 2 + 0], v1 = en4[tid * 2 + 1];
        *reinterpret_cast<float4*>(&ens[tid * 8 + 0]) = v0;
        *reinterpret_cast<float4*>(&ens[tid * 8 + 4]) = v1;
    }

    // load A tile (64 tokens x 256 d), transposed into Asm[d][tok]
    const float4* Ag = reinterpret_cast<const float4*>(g_res + (size_t)m0 * DD);
    #pragma unroll
    for (int i = 0; i < 16; i++) {
        int f = tid + 256 * i;               // 4096 float4s
        int tok = f >> 6, seg = f & 63;
        float4 v = Ag[tok * 64 + seg];
        int db = seg * 4;
        Asm[(db + 0) * APAD + tok] = v.x;
        Asm[(db + 1) * APAD + tok] = v.y;
        Asm[(db + 2) * APAD + tok] = v.z;
        Asm[(db + 3) * APAD + tok] = v.w;
    }
    if (tid < 64) xxs[tid] = g_xx[m0 + tid];

    const float4* E4 = reinterpret_cast<const float4*>(Ecb);
    // full loadB for chunk 0 only (prologue)
    {
        int row = tid;                        // nt=0
        #pragma unroll
        for (int j = 0; j < 4; j++) {
            float4 v = E4[(size_t)row * 64 + j];
            Bs[(j * 4 + 0) * BPAD + tid] = v.x;
            Bs[(j * 4 + 1) * BPAD + tid] = v.y;
            Bs[(j * 4 + 2) * BPAD + tid] = v.z;
            Bs[(j * 4 + 3) * BPAD + tid] = v.w;
        }
    }
    __syncthreads();

    float mv[8]; int mi[8];
    #pragma unroll
    for (int r = 0; r < 8; r++) { mv[r] = INFINITY; mi[r] = 0; }
    unsigned long long acc[8][4];
    #pragma unroll
    for (int r = 0; r < 8; r++)
        #pragma unroll
        for (int q = 0; q < 4; q++) acc[r][q] = 0ull;

    for (int cc = 0; cc < 128; cc++) {             // 8 n-tiles * 16 d-chunks
        const float* Bp = Bs + (cc & 1) * 16 * BPAD;
        float* nbuf = Bs + ((cc + 1) & 1) * 16 * BPAD;
        const float4* src = nullptr;
        if (cc + 1 < 128) {
            int nt = (cc + 1) >> 4, dc = (cc + 1) & 15;
            src = &E4[(size_t)(nt * 256 + tid) * 64 + dc * 4];
        }
        int dbase = (cc & 15) * 16;

        float4 p0, p1;
        if (src) { p0 = src[0]; p1 = src[1]; }     // prefetch rows 0..7

        #pragma unroll
        for (int kk = 0; kk < 16; kk++) {
            // b: 8 codewords as 4 f32x2 (two LDS.128)
            const unsigned long long* br =
                reinterpret_cast<const unsigned long long*>(&Bp[kk * BPAD]);
            ulonglong2 bb0 = *reinterpret_cast<const ulonglong2*>(&br[lane * 2]);
            ulonglong2 bb1 = *reinterpret_cast<const ulonglong2*>(&br[64 + lane * 2]);
            // a: 8 token values (broadcast LDS.128 x2)
            float4 av0 = *reinterpret_cast<const float4*>(&Asm[(dbase + kk) * APAD + wy * 8]);
            float4 av1 = *reinterpret_cast<const float4*>(&Asm[(dbase + kk) * APAD + wy * 8 + 4]);
            float a[8] = {av0.x, av0.y, av0.z, av0.w, av1.x, av1.y, av1.z, av1.w};
            #pragma unroll
            for (int r = 0; r < 8; r++) {
                unsigned long long a2 = dup2(a[r]);
                fma2(acc[r][0], a2, bb0.x);
                fma2(acc[r][1], a2, bb0.y);
                fma2(acc[r][2], a2, bb1.x);
                fma2(acc[r][3], a2, bb1.y);
            }
            if (kk == 7 && src) {                  // drain stage 1, prefetch stage 2
                nbuf[0 * BPAD + tid] = p0.x;
                nbuf[1 * BPAD + tid] = p0.y;
                nbuf[2 * BPAD + tid] = p0.z;
                nbuf[3 * BPAD + tid] = p0.w;
                nbuf[4 * BPAD + tid] = p1.x;
                nbuf[5 * BPAD + tid] = p1.y;
                nbuf[6 * BPAD + tid] = p1.z;
                nbuf[7 * BPAD + tid] = p1.w;
                p0 = src[2]; p1 = src[3];
            }
        }
        if (src) {                                 // drain stage 2
            nbuf[8  * BPAD + tid] = p0.x;
            nbuf[9  * BPAD + tid] = p0.y;
            nbuf[10 * BPAD + tid] = p0.z;
            nbuf[11 * BPAD + tid] = p0.w;
            nbuf[12 * BPAD + tid] = p1.x;
            nbuf[13 * BPAD + tid] = p1.y;
            nbuf[14 * BPAD + tid] = p1.z;
            nbuf[15 * BPAD + tid] = p1.w;
        }

        if ((cc & 15) == 15) {                     // n-tile complete: argmin epilogue
            int n0 = (cc >> 4) * 256;
            float2 e01[4];
            #pragma unroll
            for (int q = 0; q < 4; q++) {
                int kb = n0 + (q >> 1) * 128 + lane * 4 + (q & 1) * 2;
                e01[q] = *reinterpret_cast<const float2*>(&ens[kb]);
            }
            #pragma unroll
            for (int r = 0; r < 8; r++) {
                float xr = xxs[wy * 8 + r];
                #pragma unroll
                for (int q = 0; q < 4; q++) {
                    int kb = n0 + (q >> 1) * 128 + lane * 4 + (q & 1) * 2;
                    float lo, hi;
                    unpk(lo, hi, acc[r][q]);
                    float s0 = (xr - 2.0f * lo) + e01[q].x;
                    float s1 = (xr - 2.0f * hi) + e01[q].y;
                    if (s0 < mv[r]) { mv[r] = s0; mi[r] = kb; }
                    if (s1 < mv[r]) { mv[r] = s1; mi[r] = kb + 1; }
                    acc[r][q] = 0ull;
                }
            }
        }
        __syncthreads();
    }

    // argmin reduce across 32 lanes (first-index tie break)
    #pragma unroll
    for (int off = 1; off < 32; off <<= 1) {
        #pragma unroll
        for (int r = 0; r < 8; r++) {
            float ov = __shfl_xor_sync(0xffffffffu, mv[r], off);
            int   oi = __shfl_xor_sync(0xffffffffu, mi[r], off);
            if (ov < mv[r] || (ov == mv[r] && oi < mi[r])) { mv[r] = ov; mi[r] = oi; }
        }
    }

    // fused straight-through update for this warp's 8 tokens
    float sl = 0.f;
    #pragma unroll
    for (int r = 0; r < 8; r++) {
        int tok = m0 + wy * 8 + r;
        int idx = mi[r];
        const float* qrow = Ecb + (size_t)idx * DD;
        float* rrow = g_res + (size_t)tok * DD;
        float* orow = out + (size_t)tok * DD;
        float sx = 0.f;
        #pragma unroll
        for (int j = 0; j < 8; j++) {
            int d = lane + 32 * j;
            float rr = rrow[d];
            float q  = __ldg(&qrow[d]);
            float df = q - rr;                 // fl(q - r)
            float zq = rr + df;                // straight-through value, jax order
            float nr = rr - zq;                // new residual
            orow[d] += zq;                     // z_q_total accumulation
            rrow[d] = nr;
            sl += df * df;
            sx += nr * nr;                     // xx for next codebook (k_xx order)
        }
        #pragma unroll
        for (int off = 16; off; off >>= 1) sx += __shfl_down_sync(0xffffffffu, sx, off);
        if (lane == 0) {
            g_xx[tok] = sx;
            out[CODES_OFF + tok * NCB + cb] = (float)idx;
        }
    }
    #pragma unroll
    for (int off = 16; off; off >>= 1) sl += __shfl_xor_sync(0xffffffffu, sl, off);
    if (lane == 0) atomicAdd(&g_vqp[cb], sl);
}

// ---------------- semantic head GEMM1: H = gelu(zq1 @ W1 + b1) ----------------
__global__ void __launch_bounds__(256, 2)
k_gemm1(const float* __restrict__ A, const float* __restrict__ W1, const float* __restrict__ b1) {
    extern __shared__ float sm[];
    float* Asm = sm;                  // [256][APAD]
    float* Bs  = sm + 256 * APAD;     // [16][APAD]
    int tid = threadIdx.x, tx = tid & 15, ty = tid >> 4;
    int m0 = blockIdx.x * 64, n0 = blockIdx.y * 64;

    const float4* Ag = reinterpret_cast<const float4*>(A + (size_t)m0 * DD);
    #pragma unroll
    for (int i = 0; i < 16; i++) {
        int f = tid + 256 * i;
        int tok = f >> 6, seg = f & 63;
        float4 v = Ag[tok * 64 + seg];
        int db = seg * 4;
        Asm[(db + 0) * APAD + tok] = v.x;
        Asm[(db + 1) * APAD + tok] = v.y;
        Asm[(db + 2) * APAD + tok] = v.z;
        Asm[(db + 3) * APAD + tok] = v.w;
    }
    __syncthreads();

    float acc[4][4];
    #pragma unroll
    for (int r = 0; r < 4; r++)
        #pragma unroll
        for (int c = 0; c < 4; c++) acc[r][c] = 0.f;

    for (int dc = 0; dc < 16; dc++) {
        int dk = tid >> 4, nseg = tid & 15;
        float4 v = *reinterpret_cast<const float4*>(&W1[(size_t)(dc * 16 + dk) * SEMD + n0 + nseg * 4]);
        *reinterpret_cast<float4*>(&Bs[dk * APAD + nseg * 4]) = v;
        __syncthreads();
        #pragma unroll
        for (int kk = 0; kk < 16; kk++) {
            float4 av = *reinterpret_cast<const float4*>(&Asm[(dc * 16 + kk) * APAD + ty * 4]);
            float4 bv = *reinterpret_cast<const float4*>(&Bs[kk * APAD + tx * 4]);
            float a[4] = {av.x, av.y, av.z, av.w};
            float b[4] = {bv.x, bv.y, bv.z, bv.w};
            #pragma unroll
            for (int r = 0; r < 4; r++)
                #pragma unroll
                for (int c = 0; c < 4; c++)
                    acc[r][c] = fmaf(a[r], b[c], acc[r][c]);
        }
        __syncthreads();
    }
    #pragma unroll
    for (int r = 0; r < 4; r++)
        #pragma unroll
        for (int c = 0; c < 4; c++) {
            int m = m0 + ty * 4 + r, n = n0 + tx * 4 + c;
            float x = acc[r][c] + __ldg(&b1[n]);
            float h = 0.5f * x * (1.0f + erff(x * 0.70710678118654752f));
            g_H[(size_t)m * SEMD + n] = h;
        }
}

// ---------------- semantic head GEMM2 + fused MSE reduction ----------------
__global__ void __launch_bounds__(256, 2)
k_gemm2(const float* __restrict__ W2, const float* __restrict__ b2, const float* __restrict__ tgt) {
    extern __shared__ float sm[];
    float* Asm = sm;
    float* Bs  = sm + 256 * APAD;
    int tid = threadIdx.x, tx = tid & 15, ty = tid >> 4;
    int m0 = blockIdx.x * 64, n0 = blockIdx.y * 64;

    const float4* Ag = reinterpret_cast<const float4*>(g_H + (size_t)m0 * SEMD);
    #pragma unroll
    for (int i = 0; i < 16; i++) {
        int f = tid + 256 * i;
        int tok = f >> 6, seg = f & 63;
        float4 v = Ag[tok * 64 + seg];
        int db = seg * 4;
        Asm[(db + 0) * APAD + tok] = v.x;
        Asm[(db + 1) * APAD + tok] = v.y;
        Asm[(db + 2) * APAD + tok] = v.z;
        Asm[(db + 3) * APAD + tok] = v.w;
    }
    __syncthreads();

    float acc[4][4];
    #pragma unroll
    for (int r = 0; r < 4; r++)
        #pragma unroll
        for (int c = 0; c < 4; c++) acc[r][c] = 0.f;

    for (int dc = 0; dc < 16; dc++) {
        int dk = tid >> 4, nseg = tid & 15;
        float4 v = *reinterpret_cast<const float4*>(&W2[(size_t)(dc * 16 + dk) * W2VD + n0 + nseg * 4]);
        *reinterpret_cast<float4*>(&Bs[dk * APAD + nseg * 4]) = v;
        __syncthreads();
        #pragma unroll
        for (int kk = 0; kk < 16; kk++) {
            float4 av = *reinterpret_cast<const float4*>(&Asm[(dc * 16 + kk) * APAD + ty * 4]);
            float4 bv = *reinterpret_cast<const float4*>(&Bs[kk * APAD + tx * 4]);
            float a[4] = {av.x, av.y, av.z, av.w};
            float b[4] = {bv.x, bv.y, bv.z, bv.w};
            #pragma unroll
            for (int r = 0; r < 4; r++)
                #pragma unroll
                for (int c = 0; c < 4; c++)
                    acc[r][c] = fmaf(a[r], b[c], acc[r][c]);
        }
        __syncthreads();
    }

    float ls = 0.f;
    #pragma unroll
    for (int r = 0; r < 4; r++)
        #pragma unroll
        for (int c = 0; c < 4; c++) {
            int m = m0 + ty * 4 + r, n = n0 + tx * 4 + c;
            float p = acc[r][c] + __ldg(&b2[n]);
            float d = p - __ldg(&tgt[(size_t)m * W2VD + n]);
            ls += d * d;
        }
    __shared__ float red[8];
    int lane = tid & 31, w = tid >> 5;
    #pragma unroll
    for (int off = 16; off; off >>= 1) ls += __shfl_xor_sync(0xffffffffu, ls, off);
    if (!lane) red[w] = ls;
    __syncthreads();
    if (tid < 8) {
        float t = red[tid];
        #pragma unroll
        for (int off = 4; off; off >>= 1) t += __shfl_xor_sync(0xffu, t, off);
        if (tid == 0) atomicAdd(&g_semsum, t);
    }
}

// ---------------- finalize scalars ----------------
__global__ void k_fin(float* __restrict__ out) {
    if (threadIdx.x == 0) {
        float vq = 0.f;
        #pragma unroll
        for (int i = 0; i < NCB; i++) {
            float m = g_vqp[i] * (1.0f / 4194304.0f);   // mean over B*T*D
            vq += m + 0.25f * m;                         // embedding + COMMIT*commitment
        }
        out[VQ_OFF] = vq;
        out[SEM_OFF] = g_semsum * (1.0f / 16777216.0f);  // mean over B*T*W2V
    }
}

// ---------------- launch ----------------
extern "C" void kernel_launch(void* const* d_in, const int* in_sizes, int n_in,
                              void* d_out, int out_size) {
    const float* z   = (const float*)d_in[0];
    const float* w2v = (const float*)d_in[1];
    const float* E   = (const float*)d_in[2];
    const float* W1  = (const float*)d_in[3];
    const float* b1  = (const float*)d_in[4];
    const float* W2  = (const float*)d_in[5];
    const float* b2  = (const float*)d_in[6];
    float* out = (float*)d_out;

    const int ARG_SMEM  = (256 * APAD + 2 * 16 * BPAD + 64 + KCB) * 4;  // 111,872 B
    const int GEMM_SMEM = (256 * APAD + 16 * APAD) * 4;                 // 73,984 B
    cudaFuncSetAttribute(k_argmin, cudaFuncAttributeMaxDynamicSharedMemorySize, ARG_SMEM);
    cudaFuncSetAttribute(k_gemm1,  cudaFuncAttributeMaxDynamicSharedMemorySize, GEMM_SMEM);
    cudaFuncSetAttribute(k_gemm2,  cudaFuncAttributeMaxDynamicSharedMemorySize, GEMM_SMEM);

    k_enorm<<<(NCB * KCB * 32 + 255) / 256, 256>>>(E);
    k_init<<<(ZQ_ELEMS + 1023) / 1024, 1024>>>(z, out);
    k_xx<<<(BT * 32 + 255) / 256, 256>>>();

    for (int cb = 0; cb < NCB; cb++) {
        const float* Ecb = E + (size_t)cb * KCB * DD;
        k_argmin<<<BT / 64, 256, ARG_SMEM>>>(Ecb, cb, out);
        if (cb == 0) {
            k_gemm1<<<dim3(BT / 64, SEMD / 64), 256, GEMM_SMEM>>>(out, W1, b1);
            k_gemm2<<<dim3(BT / 64, W2VD / 64), 256, GEMM_SMEM>>>(W2, b2, w2v);
        }
    }
    k_fin<<<1, 32>>>(out);
}

// round 5
// speedup vs baseline: 1.4999x; 1.0792x over previous
#include <cuda_runtime.h>
#include <math.h>

#define NCB   10
#define KCB   2048
#define DD    256
#define SEMD  256
#define W2VD  1024
#define BT    16384              // B*T tokens
#define ZQ_ELEMS (BT*DD)         // 4194304
#define CODES_OFF ZQ_ELEMS
#define VQ_OFF   (CODES_OFF + BT*NCB)
#define SEM_OFF  (VQ_OFF + 1)
#define APAD  68                 // A smem row stride (floats, 16B aligned)
#define BPAD  264                // B smem row stride (floats, 16B aligned)

// -------- device scratch (no runtime allocation allowed) --------
__device__ float g_res[ZQ_ELEMS];     // residual, 16 MB
__device__ float g_H[BT*SEMD];        // semantic hidden, 16 MB
__device__ float g_Et[NCB*DD*KCB];    // E transposed per codebook: [cb][d][k], 20 MB
__device__ float g_en[NCB*KCB];       // ||e_k||^2 per codebook
__device__ float g_xx[BT];            // ||x||^2 per token (current residual)
__device__ float g_vqp[NCB];          // per-codebook sum of (q-r)^2
__device__ float g_semsum;            // sum of (pred-target)^2

// packed fp32x2 FMA (sm_103a): two bitwise-exact IEEE fp32 FMAs per issue slot
__device__ __forceinline__ void fma2(unsigned long long& d,
                                     unsigned long long a, unsigned long long b) {
    asm("fma.rn.f32x2 %0, %1, %2, %0;" : "+l"(d) : "l"(a), "l"(b));
}
__device__ __forceinline__ unsigned long long dup2(float a) {
    unsigned long long r;
    asm("mov.b64 %0, {%1, %1};" : "=l"(r) : "f"(a));
    return r;
}
__device__ __forceinline__ void unpk(float& lo, float& hi, unsigned long long v) {
    asm("mov.b64 {%0, %1}, %2;" : "=f"(lo), "=f"(hi) : "l"(v));
}
__device__ __forceinline__ void cp16(void* smem_dst, const void* gsrc) {
    unsigned s = (unsigned)__cvta_generic_to_shared(smem_dst);
    asm volatile("cp.async.cg.shared.global [%0], [%1], 16;" :: "r"(s), "l"(gsrc));
}

// ---------------- E transpose: g_Et[cb][d][k] = E[cb][k][d] ----------------
__global__ void k_trans(const float* __restrict__ E) {
    __shared__ float tile[64][65];
    int kt = blockIdx.x, dt = blockIdx.y, cb = blockIdx.z;
    int tid = threadIdx.x;
    const float* Ein = E + (size_t)cb * KCB * DD;
    float* Eout = g_Et + (size_t)cb * DD * KCB;
    #pragma unroll
    for (int i = 0; i < 16; i++) {
        int idx = i * 256 + tid;
        int r = idx >> 6, c = idx & 63;
        tile[r][c] = Ein[(size_t)(kt * 64 + r) * DD + dt * 64 + c];
    }
    __syncthreads();
    #pragma unroll
    for (int i = 0; i < 16; i++) {
        int idx = i * 256 + tid;
        int r = idx >> 6, c = idx & 63;
        Eout[(size_t)(dt * 64 + r) * KCB + kt * 64 + c] = tile[c][r];
    }
}

// ---------------- codeword norms ----------------
__global__ void k_enorm(const float* __restrict__ E) {
    int w = (blockIdx.x * blockDim.x + threadIdx.x) >> 5;
    int lane = threadIdx.x & 31;
    if (w >= NCB * KCB) return;
    const float* e = E + (size_t)w * DD;
    float s = 0.f;
    #pragma unroll
    for (int k = 0; k < 8; k++) { float v = e[lane + 32 * k]; s += v * v; }
    #pragma unroll
    for (int off = 16; off; off >>= 1) s += __shfl_down_sync(0xffffffffu, s, off);
    if (!lane) g_en[w] = s;
}

// ---------------- init: residual = z, zero accumulators + z_q region ----------------
__global__ void k_init(const float* __restrict__ z, float* __restrict__ out) {
    int i = blockIdx.x * blockDim.x + threadIdx.x;
    if (i < ZQ_ELEMS) { g_res[i] = z[i]; out[i] = 0.f; }
    if (i < NCB) g_vqp[i] = 0.f;
    if (i == NCB) g_semsum = 0.f;
}

// ---------------- ||x||^2 per token (initial only; later fused) ----------------
__global__ void k_xx() {
    int w = (blockIdx.x * blockDim.x + threadIdx.x) >> 5;
    int lane = threadIdx.x & 31;
    if (w >= BT) return;
    const float* row = g_res + (size_t)w * DD;
    float s = 0.f;
    #pragma unroll
    for (int k = 0; k < 8; k++) { float v = row[lane + 32 * k]; s += v * v; }
    #pragma unroll
    for (int off = 16; off; off >>= 1) s += __shfl_down_sync(0xffffffffu, s, off);
    if (!lane) g_xx[w] = s;
}

// ---------------- fused argmin GEMM + straight-through update ----------------
// block = 256 threads = 8 warps. Warp wy owns tokens [m0+wy*8, +8).
// Thread: 8 tokens x 8 codewords. K swept in 8 n-tiles of 256 cw; d in 16
// chunks of 16 per n-tile. B chunks stream from pre-transposed g_Et via
// cp.async double-buffering; bb operands manually prefetched across kk.
__global__ void __launch_bounds__(256, 2)
k_argmin(int cb, float* __restrict__ out) {
    extern __shared__ float sm[];
    float* Asm = sm;                        // [256 d][APAD]  (token minor)
    float* Bs  = sm + 256 * APAD;           // 2 x [16 d][BPAD] (cw minor)
    float* xxs = Bs + 2 * 16 * BPAD;        // [64]
    float* ens = xxs + 64;                  // [2048] codeword norms

    int tid = threadIdx.x;
    int lane = tid & 31, wy = tid >> 5;
    int m0 = blockIdx.x * 64;
    const float* Et = g_Et + (size_t)cb * DD * KCB;
    const float* Ecb0 = nullptr;            // set later for update gather

    // issue one 16d x 256cw B chunk (16 KB) via cp.async, then commit
    auto issueB = [&](int cc, float* buf) {
        int nt = cc >> 4, dc = cc & 15;
        #pragma unroll
        for (int i = 0; i < 4; i++) {
            int fid = i * 256 + tid;
            int row = fid >> 6, col = (fid & 63) * 4;
            cp16(&buf[row * BPAD + col],
                 Et + (size_t)(dc * 16 + row) * KCB + nt * 256 + col);
        }
        asm volatile("cp.async.commit_group;");
    };

    issueB(0, Bs);                          // prologue: chunk 0 in flight

    // stage codeword norms for this codebook into smem (2048 floats)
    {
        const float4* en4 = reinterpret_cast<const float4*>(g_en + cb * KCB);
        float4 v0 = en4[tid * 2 + 0], v1 = en4[tid * 2 + 1];
        *reinterpret_cast<float4*>(&ens[tid * 8 + 0]) = v0;
        *reinterpret_cast<float4*>(&ens[tid * 8 + 4]) = v1;
    }

    // load A tile (64 tokens x 256 d), transposed into Asm[d][tok]
    const float4* Ag = reinterpret_cast<const float4*>(g_res + (size_t)m0 * DD);
    #pragma unroll
    for (int i = 0; i < 16; i++) {
        int f = tid + 256 * i;               // 4096 float4s
        int tok = f >> 6, seg = f & 63;
        float4 v = Ag[tok * 64 + seg];
        int db = seg * 4;
        Asm[(db + 0) * APAD + tok] = v.x;
        Asm[(db + 1) * APAD + tok] = v.y;
        Asm[(db + 2) * APAD + tok] = v.z;
        Asm[(db + 3) * APAD + tok] = v.w;
    }
    if (tid < 64) xxs[tid] = g_xx[m0 + tid];

    float mv[8]; int mi[8];
    #pragma unroll
    for (int r = 0; r < 8; r++) { mv[r] = INFINITY; mi[r] = 0; }
    unsigned long long acc[8][4];
    #pragma unroll
    for (int r = 0; r < 8; r++)
        #pragma unroll
        for (int q = 0; q < 4; q++) acc[r][q] = 0ull;

    for (int cc = 0; cc < 128; cc++) {             // 8 n-tiles * 16 d-chunks
        asm volatile("cp.async.wait_group 0;");    // chunk cc landed
        __syncthreads();                           // visibility + WAR on other buf
        if (cc + 1 < 128) issueB(cc + 1, Bs + ((cc + 1) & 1) * 16 * BPAD);

        const float* Bp = Bs + (cc & 1) * 16 * BPAD;
        int dbase = (cc & 15) * 16;

        // preload kk=0 operands
        ulonglong2 bb0 = *reinterpret_cast<const ulonglong2*>(
            reinterpret_cast<const unsigned long long*>(&Bp[0]) + lane * 2);
        ulonglong2 bb1 = *reinterpret_cast<const ulonglong2*>(
            reinterpret_cast<const unsigned long long*>(&Bp[0]) + 64 + lane * 2);

        #pragma unroll
        for (int kk = 0; kk < 16; kk++) {
            ulonglong2 nb0, nb1;
            if (kk < 15) {                          // prefetch kk+1's b operands
                const unsigned long long* brn =
                    reinterpret_cast<const unsigned long long*>(&Bp[(kk + 1) * BPAD]);
                nb0 = *reinterpret_cast<const ulonglong2*>(brn + lane * 2);
                nb1 = *reinterpret_cast<const ulonglong2*>(brn + 64 + lane * 2);
            }
            // a: 8 token values (broadcast LDS.128 x2)
            float4 av0 = *reinterpret_cast<const float4*>(&Asm[(dbase + kk) * APAD + wy * 8]);
            float4 av1 = *reinterpret_cast<const float4*>(&Asm[(dbase + kk) * APAD + wy * 8 + 4]);
            float a[8] = {av0.x, av0.y, av0.z, av0.w, av1.x, av1.y, av1.z, av1.w};
            #pragma unroll
            for (int r = 0; r < 8; r++) {
                unsigned long long a2 = dup2(a[r]);
                fma2(acc[r][0], a2, bb0.x);
                fma2(acc[r][1], a2, bb0.y);
                fma2(acc[r][2], a2, bb1.x);
                fma2(acc[r][3], a2, bb1.y);
            }
            if (kk < 15) { bb0 = nb0; bb1 = nb1; }
        }

        if ((cc & 15) == 15) {                     // n-tile complete: argmin epilogue
            int n0 = (cc >> 4) * 256;
            float2 e01[4];
            #pragma unroll
            for (int q = 0; q < 4; q++) {
                int kb = n0 + (q >> 1) * 128 + lane * 4 + (q & 1) * 2;
                e01[q] = *reinterpret_cast<const float2*>(&ens[kb]);
            }
            #pragma unroll
            for (int r = 0; r < 8; r++) {
                float xr = xxs[wy * 8 + r];
                #pragma unroll
                for (int q = 0; q < 4; q++) {
                    int kb = n0 + (q >> 1) * 128 + lane * 4 + (q & 1) * 2;
                    float lo, hi;
                    unpk(lo, hi, acc[r][q]);
                    float s0 = (xr - 2.0f * lo) + e01[q].x;
                    float s1 = (xr - 2.0f * hi) + e01[q].y;
                    if (s0 < mv[r]) { mv[r] = s0; mi[r] = kb; }
                    if (s1 < mv[r]) { mv[r] = s1; mi[r] = kb + 1; }
                    acc[r][q] = 0ull;
                }
            }
        }
    }

    // argmin reduce across 32 lanes (first-index tie break)
    #pragma unroll
    for (int off = 1; off < 32; off <<= 1) {
        #pragma unroll
        for (int r = 0; r < 8; r++) {
            float ov = __shfl_xor_sync(0xffffffffu, mv[r], off);
            int   oi = __shfl_xor_sync(0xffffffffu, mi[r], off);
            if (ov < mv[r] || (ov == mv[r] && oi < mi[r])) { mv[r] = ov; mi[r] = oi; }
        }
    }

    // fused straight-through update for this warp's 8 tokens
    // gather codewords from original-layout E via g_Et? No: use row gather from
    // transposed layout is strided; keep original E rows via g_Et's source...
    // E original pointer reconstructed from argument-free path: use Et-transposed
    // gather: q[d] = Et[d*KCB + idx] (stride KCB — coalesced across lanes? lane
    // varies d -> stride KCB*4 bytes: NOT coalesced). Instead gather from E
    // original layout, passed through g_en? Use global E pointer stored below.
    float sl = 0.f;
    #pragma unroll
    for (int r = 0; r < 8; r++) {
        int tok = m0 + wy * 8 + r;
        int idx = mi[r];
        float* rrow = g_res + (size_t)tok * DD;
        float* orow = out + (size_t)tok * DD;
        float sx = 0.f;
        #pragma unroll
        for (int j = 0; j < 8; j++) {
            int d = lane + 32 * j;
            float rr = rrow[d];
            float q  = __ldg(&Et[(size_t)d * KCB + idx]);   // Et[d][idx] == E[idx][d]
            float df = q - rr;                 // fl(q - r)
            float zq = rr + df;                // straight-through value, jax order
            float nr = rr - zq;                // new residual
            orow[d] += zq;                     // z_q_total accumulation
            rrow[d] = nr;
            sl += df * df;
            sx += nr * nr;                     // xx for next codebook (k_xx order)
        }
        #pragma unroll
        for (int off = 16; off; off >>= 1) sx += __shfl_down_sync(0xffffffffu, sx, off);
        if (lane == 0) {
            g_xx[tok] = sx;
            out[CODES_OFF + tok * NCB + cb] = (float)idx;
        }
    }
    #pragma unroll
    for (int off = 16; off; off >>= 1) sl += __shfl_xor_sync(0xffffffffu, sl, off);
    if (lane == 0) atomicAdd(&g_vqp[cb], sl);
    (void)Ecb0;
}

// ---------------- semantic head GEMM1: H = gelu(zq1 @ W1 + b1) ----------------
__global__ void __launch_bounds__(256, 2)
k_gemm1(const float* __restrict__ A, const float* __restrict__ W1, const float* __restrict__ b1) {
    extern __shared__ float sm[];
    float* Asm = sm;                  // [256][APAD]
    float* Bs  = sm + 256 * APAD;     // [16][APAD]
    int tid = threadIdx.x, tx = tid & 15, ty = tid >> 4;
    int m0 = blockIdx.x * 64, n0 = blockIdx.y * 64;

    const float4* Ag = reinterpret_cast<const float4*>(A + (size_t)m0 * DD);
    #pragma unroll
    for (int i = 0; i < 16; i++) {
        int f = tid + 256 * i;
        int tok = f >> 6, seg = f & 63;
        float4 v = Ag[tok * 64 + seg];
        int db = seg * 4;
        Asm[(db + 0) * APAD + tok] = v.x;
        Asm[(db + 1) * APAD + tok] = v.y;
        Asm[(db + 2) * APAD + tok] = v.z;
        Asm[(db + 3) * APAD + tok] = v.w;
    }
    __syncthreads();

    float acc[4][4];
    #pragma unroll
    for (int r = 0; r < 4; r++)
        #pragma unroll
        for (int c = 0; c < 4; c++) acc[r][c] = 0.f;

    for (int dc = 0; dc < 16; dc++) {
        int dk = tid >> 4, nseg = tid & 15;
        float4 v = *reinterpret_cast<const float4*>(&W1[(size_t)(dc * 16 + dk) * SEMD + n0 + nseg * 4]);
        *reinterpret_cast<float4*>(&Bs[dk * APAD + nseg * 4]) = v;
        __syncthreads();
        #pragma unroll
        for (int kk = 0; kk < 16; kk++) {
            float4 av = *reinterpret_cast<const float4*>(&Asm[(dc * 16 + kk) * APAD + ty * 4]);
            float4 bv = *reinterpret_cast<const float4*>(&Bs[kk * APAD + tx * 4]);
            float a[4] = {av.x, av.y, av.z, av.w};
            float b[4] = {bv.x, bv.y, bv.z, bv.w};
            #pragma unroll
            for (int r = 0; r < 4; r++)
                #pragma unroll
                for (int c = 0; c < 4; c++)
                    acc[r][c] = fmaf(a[r], b[c], acc[r][c]);
        }
        __syncthreads();
    }
    #pragma unroll
    for (int r = 0; r < 4; r++)
        #pragma unroll
        for (int c = 0; c < 4; c++) {
            int m = m0 + ty * 4 + r, n = n0 + tx * 4 + c;
            float x = acc[r][c] + __ldg(&b1[n]);
            float h = 0.5f * x * (1.0f + erff(x * 0.70710678118654752f));
            g_H[(size_t)m * SEMD + n] = h;
        }
}

// ---------------- semantic head GEMM2 + fused MSE reduction ----------------
__global__ void __launch_bounds__(256, 2)
k_gemm2(const float* __restrict__ W2, const float* __restrict__ b2, const float* __restrict__ tgt) {
    extern __shared__ float sm[];
    float* Asm = sm;
    float* Bs  = sm + 256 * APAD;
    int tid = threadIdx.x, tx = tid & 15, ty = tid >> 4;
    int m0 = blockIdx.x * 64, n0 = blockIdx.y * 64;

    const float4* Ag = reinterpret_cast<const float4*>(g_H + (size_t)m0 * SEMD);
    #pragma unroll
    for (int i = 0; i < 16; i++) {
        int f = tid + 256 * i;
        int tok = f >> 6, seg = f & 63;
        float4 v = Ag[tok * 64 + seg];
        int db = seg * 4;
        Asm[(db + 0) * APAD + tok] = v.x;
        Asm[(db + 1) * APAD + tok] = v.y;
        Asm[(db + 2) * APAD + tok] = v.z;
        Asm[(db + 3) * APAD + tok] = v.w;
    }
    __syncthreads();

    float acc[4][4];
    #pragma unroll
    for (int r = 0; r < 4; r++)
        #pragma unroll
        for (int c = 0; c < 4; c++) acc[r][c] = 0.f;

    for (int dc = 0; dc < 16; dc++) {
        int dk = tid >> 4, nseg = tid & 15;
        float4 v = *reinterpret_cast<const float4*>(&W2[(size_t)(dc * 16 + dk) * W2VD + n0 + nseg * 4]);
        *reinterpret_cast<float4*>(&Bs[dk * APAD + nseg * 4]) = v;
        __syncthreads();
        #pragma unroll
        for (int kk = 0; kk < 16; kk++) {
            float4 av = *reinterpret_cast<const float4*>(&Asm[(dc * 16 + kk) * APAD + ty * 4]);
            float4 bv = *reinterpret_cast<const float4*>(&Bs[kk * APAD + tx * 4]);
            float a[4] = {av.x, av.y, av.z, av.w};
            float b[4] = {bv.x, bv.y, bv.z, bv.w};
            #pragma unroll
            for (int r = 0; r < 4; r++)
                #pragma unroll
                for (int c = 0; c < 4; c++)
                    acc[r][c] = fmaf(a[r], b[c], acc[r][c]);
        }
        __syncthreads();
    }

    float ls = 0.f;
    #pragma unroll
    for (int r = 0; r < 4; r++)
        #pragma unroll
        for (int c = 0; c < 4; c++) {
            int m = m0 + ty * 4 + r, n = n0 + tx * 4 + c;
            float p = acc[r][c] + __ldg(&b2[n]);
            float d = p - __ldg(&tgt[(size_t)m * W2VD + n]);
            ls += d * d;
        }
    __shared__ float red[8];
    int lane = tid & 31, w = tid >> 5;
    #pragma unroll
    for (int off = 16; off; off >>= 1) ls += __shfl_xor_sync(0xffffffffu, ls, off);
    if (!lane) red[w] = ls;
    __syncthreads();
    if (tid < 8) {
        float t = red[tid];
        #pragma unroll
        for (int off = 4; off; off >>= 1) t += __shfl_xor_sync(0xffu, t, off);
        if (tid == 0) atomicAdd(&g_semsum, t);
    }
}

// ---------------- finalize scalars ----------------
__global__ void k_fin(float* __restrict__ out) {
    if (threadIdx.x == 0) {
        float vq = 0.f;
        #pragma unroll
        for (int i = 0; i < NCB; i++) {
            float m = g_vqp[i] * (1.0f / 4194304.0f);   // mean over B*T*D
            vq += m + 0.25f * m;                         // embedding + COMMIT*commitment
        }
        out[VQ_OFF] = vq;
        out[SEM_OFF] = g_semsum * (1.0f / 16777216.0f);  // mean over B*T*W2V
    }
}

// ---------------- launch ----------------
extern "C" void kernel_launch(void* const* d_in, const int* in_sizes, int n_in,
                              void* d_out, int out_size) {
    const float* z   = (const float*)d_in[0];
    const float* w2v = (const float*)d_in[1];
    const float* E   = (const float*)d_in[2];
    const float* W1  = (const float*)d_in[3];
    const float* b1  = (const float*)d_in[4];
    const float* W2  = (const float*)d_in[5];
    const float* b2  = (const float*)d_in[6];
    float* out = (float*)d_out;

    const int ARG_SMEM  = (256 * APAD + 2 * 16 * BPAD + 64 + KCB) * 4;  // 111,872 B
    const int GEMM_SMEM = (256 * APAD + 16 * APAD) * 4;                 // 73,984 B
    cudaFuncSetAttribute(k_argmin, cudaFuncAttributeMaxDynamicSharedMemorySize, ARG_SMEM);
    cudaFuncSetAttribute(k_gemm1,  cudaFuncAttributeMaxDynamicSharedMemorySize, GEMM_SMEM);
    cudaFuncSetAttribute(k_gemm2,  cudaFuncAttributeMaxDynamicSharedMemorySize, GEMM_SMEM);

    k_trans<<<dim3(KCB / 64, DD / 64, NCB), 256>>>(E);
    k_enorm<<<(NCB * KCB * 32 + 255) / 256, 256>>>(E);
    k_init<<<(ZQ_ELEMS + 1023) / 1024, 1024>>>(z, out);
    k_xx<<<(BT * 32 + 255) / 256, 256>>>();

    for (int cb = 0; cb < NCB; cb++) {
        k_argmin<<<BT / 64, 256, ARG_SMEM>>>(cb, out);
        if (cb == 0) {
            k_gemm1<<<dim3(BT / 64, SEMD / 64), 256, GEMM_SMEM>>>(out, W1, b1);
            k_gemm2<<<dim3(BT / 64, W2VD / 64), 256, GEMM_SMEM>>>(W2, b2, w2v);
        }
    }
    k_fin<<<1, 32>>>(out);
}

// round 6
// speedup vs baseline: 1.6892x; 1.1262x over previous
#include <cuda_runtime.h>
#include <math.h>

#define NCB   10
#define KCB   2048
#define DD    256
#define SEMD  256
#define W2VD  1024
#define BT    16384              // B*T tokens
#define ZQ_ELEMS (BT*DD)         // 4194304
#define CODES_OFF ZQ_ELEMS
#define VQ_OFF   (CODES_OFF + BT*NCB)
#define SEM_OFF  (VQ_OFF + 1)
#define APAD  68                 // A smem row stride (floats, 16B aligned)
#define BPAD  264                // B smem row stride (floats, 16B aligned)

// -------- device scratch (no runtime allocation allowed) --------
__device__ float g_zq1[ZQ_ELEMS];     // z_q of codebook 0 (semantic head input), 16 MB
__device__ float g_H[BT*SEMD];        // semantic hidden, 16 MB
__device__ float g_Et[NCB*DD*KCB];    // E transposed per codebook: [cb][d][k], 20 MB
__device__ float g_en[NCB*KCB];       // ||e_k||^2 per codebook
__device__ float g_vqp[NCB];          // per-codebook sum of (q-r)^2
__device__ float g_semsum;            // sum of (pred-target)^2

// packed fp32x2 FMA (sm_103a): two bitwise-exact IEEE fp32 FMAs per issue slot
__device__ __forceinline__ void fma2(unsigned long long& d,
                                     unsigned long long a, unsigned long long b) {
    asm("fma.rn.f32x2 %0, %1, %2, %0;" : "+l"(d) : "l"(a), "l"(b));
}
__device__ __forceinline__ unsigned long long dup2(float a) {
    unsigned long long r;
    asm("mov.b64 %0, {%1, %1};" : "=l"(r) : "f"(a));
    return r;
}
__device__ __forceinline__ void unpk(float& lo, float& hi, unsigned long long v) {
    asm("mov.b64 {%0, %1}, %2;" : "=f"(lo), "=f"(hi) : "l"(v));
}
__device__ __forceinline__ void cp16(void* smem_dst, const void* gsrc) {
    unsigned s = (unsigned)__cvta_generic_to_shared(smem_dst);
    asm volatile("cp.async.cg.shared.global [%0], [%1], 16;" :: "r"(s), "l"(gsrc));
}

// ---------------- E transpose: g_Et[cb][d][k] = E[cb][k][d] ----------------
__global__ void k_trans(const float* __restrict__ E) {
    __shared__ float tile[64][65];
    int kt = blockIdx.x, dt = blockIdx.y, cb = blockIdx.z;
    int tid = threadIdx.x;
    const float* Ein = E + (size_t)cb * KCB * DD;
    float* Eout = g_Et + (size_t)cb * DD * KCB;
    #pragma unroll
    for (int i = 0; i < 16; i++) {
        int idx = i * 256 + tid;
        int r = idx >> 6, c = idx & 63;
        tile[r][c] = Ein[(size_t)(kt * 64 + r) * DD + dt * 64 + c];
    }
    __syncthreads();
    #pragma unroll
    for (int i = 0; i < 16; i++) {
        int idx = i * 256 + tid;
        int r = idx >> 6, c = idx & 63;
        Eout[(size_t)(dt * 64 + r) * KCB + kt * 64 + c] = tile[c][r];
    }
}

// ---------------- codeword norms ----------------
__global__ void k_enorm(const float* __restrict__ E) {
    int w = (blockIdx.x * blockDim.x + threadIdx.x) >> 5;
    int lane = threadIdx.x & 31;
    if (w >= NCB * KCB) return;
    const float* e = E + (size_t)w * DD;
    float s = 0.f;
    #pragma unroll
    for (int k = 0; k < 8; k++) { float v = e[lane + 32 * k]; s += v * v; }
    #pragma unroll
    for (int off = 16; off; off >>= 1) s += __shfl_down_sync(0xffffffffu, s, off);
    if (!lane) g_en[w] = s;
}

// ---------------- init: zero z_q region + accumulators ----------------
__global__ void k_init(float* __restrict__ out) {
    int i = blockIdx.x * blockDim.x + threadIdx.x;
    if (i < ZQ_ELEMS) out[i] = 0.f;
    if (i < NCB) g_vqp[i] = 0.f;
    if (i == NCB) g_semsum = 0.f;
}

// ---------------- fully fused RVQ: all 10 codebooks in one launch ----------------
// block = 256 threads = 8 warps, 64 tokens per CTA. Residual lives in the smem
// A-tile for the whole kernel (per-warp-private token columns). Per codebook:
// stream Et chunks via cp.async double-buffer, FMA2 GEMM, argmin, in-smem
// straight-through update. Only z_q/codes/losses leave the CTA.
__global__ void __launch_bounds__(256, 2)
k_rvq(const float* __restrict__ z, const float* __restrict__ E, float* __restrict__ out) {
    extern __shared__ float sm[];
    float* Asm = sm;                        // [256 d][APAD]  (token minor) = residual
    float* Bs  = sm + 256 * APAD;           // 2 x [16 d][BPAD] (cw minor)
    float* xxs = Bs + 2 * 16 * BPAD;        // [64] ||residual||^2 per token
    float* ens = xxs + 64;                  // [2048] codeword norms

    int tid = threadIdx.x;
    int lane = tid & 31, wy = tid >> 5;
    int m0 = blockIdx.x * 64;

    // load A tile (64 tokens x 256 d) from z, transposed into Asm[d][tok]
    const float4* Ag = reinterpret_cast<const float4*>(z + (size_t)m0 * DD);
    #pragma unroll
    for (int i = 0; i < 16; i++) {
        int f = tid + 256 * i;               // 4096 float4s
        int tok = f >> 6, seg = f & 63;
        float4 v = Ag[tok * 64 + seg];
        int db = seg * 4;
        Asm[(db + 0) * APAD + tok] = v.x;
        Asm[(db + 1) * APAD + tok] = v.y;
        Asm[(db + 2) * APAD + tok] = v.z;
        Asm[(db + 3) * APAD + tok] = v.w;
    }

    // initial ||x||^2 per token (k_xx order: ascending j, shfl_down tree)
    #pragma unroll
    for (int r = 0; r < 8; r++) {
        int tok = m0 + wy * 8 + r;
        const float* row = z + (size_t)tok * DD;
        float s = 0.f;
        #pragma unroll
        for (int k = 0; k < 8; k++) { float v = row[lane + 32 * k]; s += v * v; }
        #pragma unroll
        for (int off = 16; off; off >>= 1) s += __shfl_down_sync(0xffffffffu, s, off);
        if (!lane) xxs[wy * 8 + r] = s;
    }

    for (int cb = 0; cb < NCB; cb++) {
        const float* Et  = g_Et + (size_t)cb * DD * KCB;
        const float* Ecb = E + (size_t)cb * KCB * DD;

        // issue one 16d x 256cw B chunk (16 KB) via cp.async, then commit
        auto issueB = [&](int cc, float* buf) {
            int nt = cc >> 4, dc = cc & 15;
            #pragma unroll
            for (int i = 0; i < 4; i++) {
                int fid = i * 256 + tid;
                int row = fid >> 6, col = (fid & 63) * 4;
                cp16(&buf[row * BPAD + col],
                     Et + (size_t)(dc * 16 + row) * KCB + nt * 256 + col);
            }
            asm volatile("cp.async.commit_group;");
        };

        issueB(0, Bs);                      // chunk 0 in flight

        // stage codeword norms for this codebook into smem (2048 floats)
        {
            const float4* en4 = reinterpret_cast<const float4*>(g_en + cb * KCB);
            float4 v0 = en4[tid * 2 + 0], v1 = en4[tid * 2 + 1];
            *reinterpret_cast<float4*>(&ens[tid * 8 + 0]) = v0;
            *reinterpret_cast<float4*>(&ens[tid * 8 + 4]) = v1;
        }

        float mv[8]; int mi[8];
        #pragma unroll
        for (int r = 0; r < 8; r++) { mv[r] = INFINITY; mi[r] = 0; }
        unsigned long long acc[8][4];
        #pragma unroll
        for (int r = 0; r < 8; r++)
            #pragma unroll
            for (int q = 0; q < 4; q++) acc[r][q] = 0ull;

        for (int cc = 0; cc < 128; cc++) {             // 8 n-tiles * 16 d-chunks
            asm volatile("cp.async.wait_group 0;");    // chunk cc landed
            __syncthreads();                           // visibility + WAR on other buf
            if (cc + 1 < 128) issueB(cc + 1, Bs + ((cc + 1) & 1) * 16 * BPAD);

            const float* Bp = Bs + (cc & 1) * 16 * BPAD;
            int dbase = (cc & 15) * 16;

            // preload kk=0 operands
            ulonglong2 bb0 = *reinterpret_cast<const ulonglong2*>(
                reinterpret_cast<const unsigned long long*>(&Bp[0]) + lane * 2);
            ulonglong2 bb1 = *reinterpret_cast<const ulonglong2*>(
                reinterpret_cast<const unsigned long long*>(&Bp[0]) + 64 + lane * 2);

            #pragma unroll
            for (int kk = 0; kk < 16; kk++) {
                ulonglong2 nb0, nb1;
                if (kk < 15) {                          // prefetch kk+1's b operands
                    const unsigned long long* brn =
                        reinterpret_cast<const unsigned long long*>(&Bp[(kk + 1) * BPAD]);
                    nb0 = *reinterpret_cast<const ulonglong2*>(brn + lane * 2);
                    nb1 = *reinterpret_cast<const ulonglong2*>(brn + 64 + lane * 2);
                }
                // a: this warp's 8 token values (broadcast LDS.128 x2)
                float4 av0 = *reinterpret_cast<const float4*>(&Asm[(dbase + kk) * APAD + wy * 8]);
                float4 av1 = *reinterpret_cast<const float4*>(&Asm[(dbase + kk) * APAD + wy * 8 + 4]);
                float a[8] = {av0.x, av0.y, av0.z, av0.w, av1.x, av1.y, av1.z, av1.w};
                #pragma unroll
                for (int r = 0; r < 8; r++) {
                    unsigned long long a2 = dup2(a[r]);
                    fma2(acc[r][0], a2, bb0.x);
                    fma2(acc[r][1], a2, bb0.y);
                    fma2(acc[r][2], a2, bb1.x);
                    fma2(acc[r][3], a2, bb1.y);
                }
                if (kk < 15) { bb0 = nb0; bb1 = nb1; }
            }

            if ((cc & 15) == 15) {                     // n-tile complete: argmin epilogue
                int n0 = (cc >> 4) * 256;
                float2 e01[4];
                #pragma unroll
                for (int q = 0; q < 4; q++) {
                    int kb = n0 + (q >> 1) * 128 + lane * 4 + (q & 1) * 2;
                    e01[q] = *reinterpret_cast<const float2*>(&ens[kb]);
                }
                #pragma unroll
                for (int r = 0; r < 8; r++) {
                    float xr = xxs[wy * 8 + r];
                    #pragma unroll
                    for (int q = 0; q < 4; q++) {
                        int kb = n0 + (q >> 1) * 128 + lane * 4 + (q & 1) * 2;
                        float lo, hi;
                        unpk(lo, hi, acc[r][q]);
                        float s0 = (xr - 2.0f * lo) + e01[q].x;
                        float s1 = (xr - 2.0f * hi) + e01[q].y;
                        if (s0 < mv[r]) { mv[r] = s0; mi[r] = kb; }
                        if (s1 < mv[r]) { mv[r] = s1; mi[r] = kb + 1; }
                        acc[r][q] = 0ull;
                    }
                }
            }
        }

        // argmin reduce across 32 lanes (first-index tie break)
        #pragma unroll
        for (int off = 1; off < 32; off <<= 1) {
            #pragma unroll
            for (int r = 0; r < 8; r++) {
                float ov = __shfl_xor_sync(0xffffffffu, mv[r], off);
                int   oi = __shfl_xor_sync(0xffffffffu, mi[r], off);
                if (ov < mv[r] || (ov == mv[r] && oi < mi[r])) { mv[r] = ov; mi[r] = oi; }
            }
        }

        // fused straight-through update, residual updated IN SMEM
        float sl = 0.f;
        #pragma unroll
        for (int r = 0; r < 8; r++) {
            int lt = wy * 8 + r;               // local token index
            int tok = m0 + lt;
            int idx = mi[r];
            const float* qrow = Ecb + (size_t)idx * DD;
            float* orow = out + (size_t)tok * DD;
            float* zrow = g_zq1 + (size_t)tok * DD;
            float sx = 0.f;
            #pragma unroll
            for (int j = 0; j < 8; j++) {
                int d = lane + 32 * j;
                float rr = Asm[d * APAD + lt];
                float q  = __ldg(&qrow[d]);
                float df = q - rr;                 // fl(q - r)
                float zq = rr + df;                // straight-through value, jax order
                float nr = rr - zq;                // new residual
                orow[d] += zq;                     // z_q_total accumulation (cb order)
                if (cb == 0) zrow[d] = zq;         // stash z_q_1 for semantic head
                Asm[d * APAD + lt] = nr;
                sl += df * df;
                sx += nr * nr;                     // xx for next codebook (k_xx order)
            }
            #pragma unroll
            for (int off = 16; off; off >>= 1) sx += __shfl_down_sync(0xffffffffu, sx, off);
            if (lane == 0) {
                xxs[lt] = sx;
                out[CODES_OFF + tok * NCB + cb] = (float)idx;
            }
        }
        #pragma unroll
        for (int off = 16; off; off >>= 1) sl += __shfl_xor_sync(0xffffffffu, sl, off);
        if (lane == 0) atomicAdd(&g_vqp[cb], sl);

        __syncthreads();   // ens/Bs WAR before next codebook restages them
    }
}

// ---------------- semantic head GEMM1: H = gelu(zq1 @ W1 + b1) ----------------
__global__ void __launch_bounds__(256, 2)
k_gemm1(const float* __restrict__ W1, const float* __restrict__ b1) {
    extern __shared__ float sm[];
    float* Asm = sm;                  // [256][APAD]
    float* Bs  = sm + 256 * APAD;     // [16][APAD]
    int tid = threadIdx.x, tx = tid & 15, ty = tid >> 4;
    int m0 = blockIdx.x * 64, n0 = blockIdx.y * 64;

    const float4* Ag = reinterpret_cast<const float4*>(g_zq1 + (size_t)m0 * DD);
    #pragma unroll
    for (int i = 0; i < 16; i++) {
        int f = tid + 256 * i;
        int tok = f >> 6, seg = f & 63;
        float4 v = Ag[tok * 64 + seg];
        int db = seg * 4;
        Asm[(db + 0) * APAD + tok] = v.x;
        Asm[(db + 1) * APAD + tok] = v.y;
        Asm[(db + 2) * APAD + tok] = v.z;
        Asm[(db + 3) * APAD + tok] = v.w;
    }
    __syncthreads();

    float acc[4][4];
    #pragma unroll
    for (int r = 0; r < 4; r++)
        #pragma unroll
        for (int c = 0; c < 4; c++) acc[r][c] = 0.f;

    for (int dc = 0; dc < 16; dc++) {
        int dk = tid >> 4, nseg = tid & 15;
        float4 v = *reinterpret_cast<const float4*>(&W1[(size_t)(dc * 16 + dk) * SEMD + n0 + nseg * 4]);
        *reinterpret_cast<float4*>(&Bs[dk * APAD + nseg * 4]) = v;
        __syncthreads();
        #pragma unroll
        for (int kk = 0; kk < 16; kk++) {
            float4 av = *reinterpret_cast<const float4*>(&Asm[(dc * 16 + kk) * APAD + ty * 4]);
            float4 bv = *reinterpret_cast<const float4*>(&Bs[kk * APAD + tx * 4]);
            float a[4] = {av.x, av.y, av.z, av.w};
            float b[4] = {bv.x, bv.y, bv.z, bv.w};
            #pragma unroll
            for (int r = 0; r < 4; r++)
                #pragma unroll
                for (int c = 0; c < 4; c++)
                    acc[r][c] = fmaf(a[r], b[c], acc[r][c]);
        }
        __syncthreads();
    }
    #pragma unroll
    for (int r = 0; r < 4; r++)
        #pragma unroll
        for (int c = 0; c < 4; c++) {
            int m = m0 + ty * 4 + r, n = n0 + tx * 4 + c;
            float x = acc[r][c] + __ldg(&b1[n]);
            float h = 0.5f * x * (1.0f + erff(x * 0.70710678118654752f));
            g_H[(size_t)m * SEMD + n] = h;
        }
}

// ---------------- semantic head GEMM2 + fused MSE reduction ----------------
__global__ void __launch_bounds__(256, 2)
k_gemm2(const float* __restrict__ W2, const float* __restrict__ b2, const float* __restrict__ tgt) {
    extern __shared__ float sm[];
    float* Asm = sm;
    float* Bs  = sm + 256 * APAD;
    int tid = threadIdx.x, tx = tid & 15, ty = tid >> 4;
    int m0 = blockIdx.x * 64, n0 = blockIdx.y * 64;

    const float4* Ag = reinterpret_cast<const float4*>(g_H + (size_t)m0 * SEMD);
    #pragma unroll
    for (int i = 0; i < 16; i++) {
        int f = tid + 256 * i;
        int tok = f >> 6, seg = f & 63;
        float4 v = Ag[tok * 64 + seg];
        int db = seg * 4;
        Asm[(db + 0) * APAD + tok] = v.x;
        Asm[(db + 1) * APAD + tok] = v.y;
        Asm[(db + 2) * APAD + tok] = v.z;
        Asm[(db + 3) * APAD + tok] = v.w;
    }
    __syncthreads();

    float acc[4][4];
    #pragma unroll
    for (int r = 0; r < 4; r++)
        #pragma unroll
        for (int c = 0; c < 4; c++) acc[r][c] = 0.f;

    for (int dc = 0; dc < 16; dc++) {
        int dk = tid >> 4, nseg = tid & 15;
        float4 v = *reinterpret_cast<const float4*>(&W2[(size_t)(dc * 16 + dk) * W2VD + n0 + nseg * 4]);
        *reinterpret_cast<float4*>(&Bs[dk * APAD + nseg * 4]) = v;
        __syncthreads();
        #pragma unroll
        for (int kk = 0; kk < 16; kk++) {
            float4 av = *reinterpret_cast<const float4*>(&Asm[(dc * 16 + kk) * APAD + ty * 4]);
            float4 bv = *reinterpret_cast<const float4*>(&Bs[kk * APAD + tx * 4]);
            float a[4] = {av.x, av.y, av.z, av.w};
            float b[4] = {bv.x, bv.y, bv.z, bv.w};
            #pragma unroll
            for (int r = 0; r < 4; r++)
                #pragma unroll
                for (int c = 0; c < 4; c++)
                    acc[r][c] = fmaf(a[r], b[c], acc[r][c]);
        }
        __syncthreads();
    }

    float ls = 0.f;
    #pragma unroll
    for (int r = 0; r < 4; r++)
        #pragma unroll
        for (int c = 0; c < 4; c++) {
            int m = m0 + ty * 4 + r, n = n0 + tx * 4 + c;
            float p = acc[r][c] + __ldg(&b2[n]);
            float d = p - __ldg(&tgt[(size_t)m * W2VD + n]);
            ls += d * d;
        }
    __shared__ float red[8];
    int lane = tid & 31, w = tid >> 5;
    #pragma unroll
    for (int off = 16; off; off >>= 1) ls += __shfl_xor_sync(0xffffffffu, ls, off);
    if (!lane) red[w] = ls;
    __syncthreads();
    if (tid < 8) {
        float t = red[tid];
        #pragma unroll
        for (int off = 4; off; off >>= 1) t += __shfl_xor_sync(0xffu, t, off);
        if (tid == 0) atomicAdd(&g_semsum, t);
    }
}

// ---------------- finalize scalars ----------------
__global__ void k_fin(float* __restrict__ out) {
    if (threadIdx.x == 0) {
        float vq = 0.f;
        #pragma unroll
        for (int i = 0; i < NCB; i++) {
            float m = g_vqp[i] * (1.0f / 4194304.0f);   // mean over B*T*D
            vq += m + 0.25f * m;                         // embedding + COMMIT*commitment
        }
        out[VQ_OFF] = vq;
        out[SEM_OFF] = g_semsum * (1.0f / 16777216.0f);  // mean over B*T*W2V
    }
}

// ---------------- launch ----------------
extern "C" void kernel_launch(void* const* d_in, const int* in_sizes, int n_in,
                              void* d_out, int out_size) {
    const float* z   = (const float*)d_in[0];
    const float* w2v = (const float*)d_in[1];
    const float* E   = (const float*)d_in[2];
    const float* W1  = (const float*)d_in[3];
    const float* b1  = (const float*)d_in[4];
    const float* W2  = (const float*)d_in[5];
    const float* b2  = (const float*)d_in[6];
    float* out = (float*)d_out;

    const int ARG_SMEM  = (256 * APAD + 2 * 16 * BPAD + 64 + KCB) * 4;  // 111,872 B
    const int GEMM_SMEM = (256 * APAD + 16 * APAD) * 4;                 // 73,984 B
    cudaFuncSetAttribute(k_rvq,   cudaFuncAttributeMaxDynamicSharedMemorySize, ARG_SMEM);
    cudaFuncSetAttribute(k_gemm1, cudaFuncAttributeMaxDynamicSharedMemorySize, GEMM_SMEM);
    cudaFuncSetAttribute(k_gemm2, cudaFuncAttributeMaxDynamicSharedMemorySize, GEMM_SMEM);

    k_trans<<<dim3(KCB / 64, DD / 64, NCB), 256>>>(E);
    k_enorm<<<(NCB * KCB * 32 + 255) / 256, 256>>>(E);
    k_init<<<(ZQ_ELEMS + 1023) / 1024, 1024>>>(out);

    k_rvq<<<BT / 64, 256, ARG_SMEM>>>(z, E, out);

    k_gemm1<<<dim3(BT / 64, SEMD / 64), 256, GEMM_SMEM>>>(W1, b1);
    k_gemm2<<<dim3(BT / 64, W2VD / 64), 256, GEMM_SMEM>>>(W2, b2, w2v);
    k_fin<<<1, 32>>>(out);
}

// round 7
// speedup vs baseline: 1.6998x; 1.0063x over previous
#include <cuda_runtime.h>
#include <math.h>

#define NCB   10
#define KCB   2048
#define DD    256
#define SEMD  256
#define W2VD  1024
#define BT    16384              // B*T tokens
#define ZQ_ELEMS (BT*DD)         // 4194304
#define CODES_OFF ZQ_ELEMS
#define VQ_OFF   (CODES_OFF + BT*NCB)
#define SEM_OFF  (VQ_OFF + 1)
#define APAD  68                 // A smem row stride (floats, 16B aligned)
#define BPAD  264                // B smem row stride (floats, 16B aligned)

// balanced tiling: 272 tiles x 56 tokens + 24 tiles x 48 tokens = 16384,
// grid = 296 = 2 x 148 SMs -> exactly one wave at occupancy 2, max 112 tok/SM
#define N56   272
#define OFF48 (N56*56)           // 15232

// -------- device scratch (no runtime allocation allowed) --------
__device__ float g_zq1[ZQ_ELEMS];     // z_q of codebook 0 (semantic head input)
__device__ float g_H[BT*SEMD];        // semantic hidden
__device__ float g_Et[NCB*DD*KCB];    // E transposed per codebook: [cb][d][k]
__device__ float g_en[NCB*KCB];       // ||e_k||^2 per codebook
__device__ float g_vqp[NCB];          // per-codebook sum of (q-r)^2
__device__ float g_semsum;            // sum of (pred-target)^2

// packed fp32x2 FMA (sm_103a): two bitwise-exact IEEE fp32 FMAs per issue slot
__device__ __forceinline__ void fma2(unsigned long long& d,
                                     unsigned long long a, unsigned long long b) {
    asm("fma.rn.f32x2 %0, %1, %2, %0;" : "+l"(d) : "l"(a), "l"(b));
}
__device__ __forceinline__ unsigned long long dup2(float a) {
    unsigned long long r;
    asm("mov.b64 %0, {%1, %1};" : "=l"(r) : "f"(a));
    return r;
}
__device__ __forceinline__ void unpk(float& lo, float& hi, unsigned long long v) {
    asm("mov.b64 {%0, %1}, %2;" : "=f"(lo), "=f"(hi) : "l"(v));
}
__device__ __forceinline__ void cp16(void* smem_dst, const void* gsrc) {
    unsigned s = (unsigned)__cvta_generic_to_shared(smem_dst);
    asm volatile("cp.async.cg.shared.global [%0], [%1], 16;" :: "r"(s), "l"(gsrc));
}

// ---------------- E transpose: g_Et[cb][d][k] = E[cb][k][d] ----------------
__global__ void k_trans(const float* __restrict__ E) {
    __shared__ float tile[64][65];
    int kt = blockIdx.x, dt = blockIdx.y, cb = blockIdx.z;
    int tid = threadIdx.x;
    const float* Ein = E + (size_t)cb * KCB * DD;
    float* Eout = g_Et + (size_t)cb * DD * KCB;
    #pragma unroll
    for (int i = 0; i < 16; i++) {
        int idx = i * 256 + tid;
        int r = idx >> 6, c = idx & 63;
        tile[r][c] = Ein[(size_t)(kt * 64 + r) * DD + dt * 64 + c];
    }
    __syncthreads();
    #pragma unroll
    for (int i = 0; i < 16; i++) {
        int idx = i * 256 + tid;
        int r = idx >> 6, c = idx & 63;
        Eout[(size_t)(dt * 64 + r) * KCB + kt * 64 + c] = tile[c][r];
    }
}

// ---------------- codeword norms ----------------
__global__ void k_enorm(const float* __restrict__ E) {
    int w = (blockIdx.x * blockDim.x + threadIdx.x) >> 5;
    int lane = threadIdx.x & 31;
    if (w >= NCB * KCB) return;
    const float* e = E + (size_t)w * DD;
    float s = 0.f;
    #pragma unroll
    for (int k = 0; k < 8; k++) { float v = e[lane + 32 * k]; s += v * v; }
    #pragma unroll
    for (int off = 16; off; off >>= 1) s += __shfl_down_sync(0xffffffffu, s, off);
    if (!lane) g_en[w] = s;
}

// ---------------- init: zero z_q region + accumulators ----------------
__global__ void k_init(float* __restrict__ out) {
    int i = blockIdx.x * blockDim.x + threadIdx.x;
    if (i < ZQ_ELEMS) out[i] = 0.f;
    if (i < NCB) g_vqp[i] = 0.f;
    if (i == NCB) g_semsum = 0.f;
}

// ---------------- fully fused RVQ body, templated on tokens-per-warp ----------------
// block = 256 threads = 8 warps; warp wy owns NR tokens (smem slots wy*8+r,
// 8-padded so all LDS patterns are NR-independent). Residual lives in smem.
template<int NR>
__device__ __forceinline__ void rvq_body(
    int m0, const float* __restrict__ z, const float* __restrict__ E,
    float* __restrict__ out, float* sm, int tid, int lane, int wy)
{
    float* Asm = sm;                        // [256 d][APAD] residual (8-padded slots)
    float* Bs  = sm + 256 * APAD;           // 2 x [16 d][BPAD]
    float* xxs = Bs + 2 * 16 * BPAD;        // [64]
    float* ens = xxs + 64;                  // [2048]

    const int mt = NR * 8;                  // tokens in this tile

    // load A tile from z, transposed into Asm[d][slot]
    const float4* Ag = reinterpret_cast<const float4*>(z + (size_t)m0 * DD);
    for (int f = tid; f < mt * 64; f += 256) {
        int tok = f >> 6, seg = f & 63;
        int slot = (tok / NR) * 8 + (tok % NR);
        float4 v = Ag[f];
        int db = seg * 4;
        Asm[(db + 0) * APAD + slot] = v.x;
        Asm[(db + 1) * APAD + slot] = v.y;
        Asm[(db + 2) * APAD + slot] = v.z;
        Asm[(db + 3) * APAD + slot] = v.w;
    }

    // initial ||x||^2 per token (ascending j, shfl_down tree)
    #pragma unroll
    for (int r = 0; r < NR; r++) {
        int tok = m0 + wy * NR + r;
        const float* row = z + (size_t)tok * DD;
        float s = 0.f;
        #pragma unroll
        for (int k = 0; k < 8; k++) { float v = row[lane + 32 * k]; s += v * v; }
        #pragma unroll
        for (int off = 16; off; off >>= 1) s += __shfl_down_sync(0xffffffffu, s, off);
        if (!lane) xxs[wy * 8 + r] = s;
    }

    for (int cb = 0; cb < NCB; cb++) {
        const float* Et  = g_Et + (size_t)cb * DD * KCB;
        const float* Ecb = E + (size_t)cb * KCB * DD;

        auto issueB = [&](int cc, float* buf) {
            int nt = cc >> 4, dc = cc & 15;
            #pragma unroll
            for (int i = 0; i < 4; i++) {
                int fid = i * 256 + tid;
                int row = fid >> 6, col = (fid & 63) * 4;
                cp16(&buf[row * BPAD + col],
                     Et + (size_t)(dc * 16 + row) * KCB + nt * 256 + col);
            }
            asm volatile("cp.async.commit_group;");
        };

        issueB(0, Bs);                      // chunk 0 in flight

        // stage codeword norms into smem
        {
            const float4* en4 = reinterpret_cast<const float4*>(g_en + cb * KCB);
            float4 v0 = en4[tid * 2 + 0], v1 = en4[tid * 2 + 1];
            *reinterpret_cast<float4*>(&ens[tid * 8 + 0]) = v0;
            *reinterpret_cast<float4*>(&ens[tid * 8 + 4]) = v1;
        }

        float mv[NR]; int mi[NR];
        #pragma unroll
        for (int r = 0; r < NR; r++) { mv[r] = INFINITY; mi[r] = 0; }
        unsigned long long acc[NR][4];
        #pragma unroll
        for (int r = 0; r < NR; r++)
            #pragma unroll
            for (int q = 0; q < 4; q++) acc[r][q] = 0ull;

        for (int cc = 0; cc < 128; cc++) {             // 8 n-tiles * 16 d-chunks
            asm volatile("cp.async.wait_group 0;");
            __syncthreads();
            if (cc + 1 < 128) issueB(cc + 1, Bs + ((cc + 1) & 1) * 16 * BPAD);

            const float* Bp = Bs + (cc & 1) * 16 * BPAD;
            int dbase = (cc & 15) * 16;

            ulonglong2 bb0 = *reinterpret_cast<const ulonglong2*>(
                reinterpret_cast<const unsigned long long*>(&Bp[0]) + lane * 2);
            ulonglong2 bb1 = *reinterpret_cast<const ulonglong2*>(
                reinterpret_cast<const unsigned long long*>(&Bp[0]) + 64 + lane * 2);

            #pragma unroll
            for (int kk = 0; kk < 16; kk++) {
                ulonglong2 nb0, nb1;
                if (kk < 15) {
                    const unsigned long long* brn =
                        reinterpret_cast<const unsigned long long*>(&Bp[(kk + 1) * BPAD]);
                    nb0 = *reinterpret_cast<const ulonglong2*>(brn + lane * 2);
                    nb1 = *reinterpret_cast<const ulonglong2*>(brn + 64 + lane * 2);
                }
                float4 av0 = *reinterpret_cast<const float4*>(&Asm[(dbase + kk) * APAD + wy * 8]);
                float4 av1 = *reinterpret_cast<const float4*>(&Asm[(dbase + kk) * APAD + wy * 8 + 4]);
                float a[8] = {av0.x, av0.y, av0.z, av0.w, av1.x, av1.y, av1.z, av1.w};
                #pragma unroll
                for (int r = 0; r < NR; r++) {
                    unsigned long long a2 = dup2(a[r]);
                    fma2(acc[r][0], a2, bb0.x);
                    fma2(acc[r][1], a2, bb0.y);
                    fma2(acc[r][2], a2, bb1.x);
                    fma2(acc[r][3], a2, bb1.y);
                }
                if (kk < 15) { bb0 = nb0; bb1 = nb1; }
            }

            if ((cc & 15) == 15) {                     // n-tile argmin epilogue
                int n0 = (cc >> 4) * 256;
                float2 e01[4];
                #pragma unroll
                for (int q = 0; q < 4; q++) {
                    int kb = n0 + (q >> 1) * 128 + lane * 4 + (q & 1) * 2;
                    e01[q] = *reinterpret_cast<const float2*>(&ens[kb]);
                }
                #pragma unroll
                for (int r = 0; r < NR; r++) {
                    float xr = xxs[wy * 8 + r];
                    #pragma unroll
                    for (int q = 0; q < 4; q++) {
                        int kb = n0 + (q >> 1) * 128 + lane * 4 + (q & 1) * 2;
                        float lo, hi;
                        unpk(lo, hi, acc[r][q]);
                        float s0 = (xr - 2.0f * lo) + e01[q].x;
                        float s1 = (xr - 2.0f * hi) + e01[q].y;
                        if (s0 < mv[r]) { mv[r] = s0; mi[r] = kb; }
                        if (s1 < mv[r]) { mv[r] = s1; mi[r] = kb + 1; }
                        acc[r][q] = 0ull;
                    }
                }
            }
        }

        // argmin reduce across 32 lanes (first-index tie break)
        #pragma unroll
        for (int off = 1; off < 32; off <<= 1) {
            #pragma unroll
            for (int r = 0; r < NR; r++) {
                float ov = __shfl_xor_sync(0xffffffffu, mv[r], off);
                int   oi = __shfl_xor_sync(0xffffffffu, mi[r], off);
                if (ov < mv[r] || (ov == mv[r] && oi < mi[r])) { mv[r] = ov; mi[r] = oi; }
            }
        }

        // fused straight-through update, residual updated IN SMEM
        float sl = 0.f;
        #pragma unroll
        for (int r = 0; r < NR; r++) {
            int slot = wy * 8 + r;
            int tok = m0 + wy * NR + r;
            int idx = mi[r];
            const float* qrow = Ecb + (size_t)idx * DD;
            float* orow = out + (size_t)tok * DD;
            float* zrow = g_zq1 + (size_t)tok * DD;
            float sx = 0.f;
            #pragma unroll
            for (int j = 0; j < 8; j++) {
                int d = lane + 32 * j;
                float rr = Asm[d * APAD + slot];
                float q  = __ldg(&qrow[d]);
                float df = q - rr;                 // fl(q - r)
                float zq = rr + df;                // straight-through, jax order
                float nr = rr - zq;                // new residual
                orow[d] += zq;                     // z_q_total accumulation
                if (cb == 0) zrow[d] = zq;         // stash z_q_1 for semantic head
                Asm[d * APAD + slot] = nr;
                sl += df * df;
                sx += nr * nr;
            }
            #pragma unroll
            for (int off = 16; off; off >>= 1) sx += __shfl_down_sync(0xffffffffu, sx, off);
            if (lane == 0) {
                xxs[slot] = sx;
                out[CODES_OFF + tok * NCB + cb] = (float)idx;
            }
        }
        #pragma unroll
        for (int off = 16; off; off >>= 1) sl += __shfl_xor_sync(0xffffffffu, sl, off);
        if (lane == 0) atomicAdd(&g_vqp[cb], sl);

        __syncthreads();   // ens/Bs WAR before next codebook restages them
    }
}

__global__ void __launch_bounds__(256, 2)
k_rvq(const float* __restrict__ z, const float* __restrict__ E, float* __restrict__ out) {
    extern __shared__ float sm[];
    int tid = threadIdx.x;
    int lane = tid & 31, wy = tid >> 5;
    int b = blockIdx.x;
    if (b < N56) rvq_body<7>(b * 56, z, E, out, sm, tid, lane, wy);
    else         rvq_body<6>(OFF48 + (b - N56) * 48, z, E, out, sm, tid, lane, wy);
}

// ---------------- semantic head GEMM1: H = gelu(zq1 @ W1 + b1) ----------------
__global__ void __launch_bounds__(256, 2)
k_gemm1(const float* __restrict__ W1, const float* __restrict__ b1) {
    extern __shared__ float sm[];
    float* Asm = sm;                  // [256][APAD]
    float* Bs  = sm + 256 * APAD;     // [16][APAD]
    int tid = threadIdx.x, tx = tid & 15, ty = tid >> 4;
    int m0 = blockIdx.x * 64, n0 = blockIdx.y * 64;

    const float4* Ag = reinterpret_cast<const float4*>(g_zq1 + (size_t)m0 * DD);
    #pragma unroll
    for (int i = 0; i < 16; i++) {
        int f = tid + 256 * i;
        int tok = f >> 6, seg = f & 63;
        float4 v = Ag[tok * 64 + seg];
        int db = seg * 4;
        Asm[(db + 0) * APAD + tok] = v.x;
        Asm[(db + 1) * APAD + tok] = v.y;
        Asm[(db + 2) * APAD + tok] = v.z;
        Asm[(db + 3) * APAD + tok] = v.w;
    }
    __syncthreads();

    unsigned long long acc[4][2];
    #pragma unroll
    for (int r = 0; r < 4; r++) { acc[r][0] = 0ull; acc[r][1] = 0ull; }

    for (int dc = 0; dc < 16; dc++) {
        int dk = tid >> 4, nseg = tid & 15;
        float4 v = *reinterpret_cast<const float4*>(&W1[(size_t)(dc * 16 + dk) * SEMD + n0 + nseg * 4]);
        *reinterpret_cast<float4*>(&Bs[dk * APAD + nseg * 4]) = v;
        __syncthreads();
        #pragma unroll
        for (int kk = 0; kk < 16; kk++) {
            float4 av = *reinterpret_cast<const float4*>(&Asm[(dc * 16 + kk) * APAD + ty * 4]);
            ulonglong2 bb = *reinterpret_cast<const ulonglong2*>(&Bs[kk * APAD + tx * 4]);
            float a[4] = {av.x, av.y, av.z, av.w};
            #pragma unroll
            for (int r = 0; r < 4; r++) {
                unsigned long long a2 = dup2(a[r]);
                fma2(acc[r][0], a2, bb.x);
                fma2(acc[r][1], a2, bb.y);
            }
        }
        __syncthreads();
    }
    #pragma unroll
    for (int r = 0; r < 4; r++)
        #pragma unroll
        for (int q = 0; q < 2; q++) {
            int m = m0 + ty * 4 + r, n = n0 + tx * 4 + q * 2;
            float lo, hi;
            unpk(lo, hi, acc[r][q]);
            float x0 = lo + __ldg(&b1[n]);
            float x1 = hi + __ldg(&b1[n + 1]);
            g_H[(size_t)m * SEMD + n]     = 0.5f * x0 * (1.0f + erff(x0 * 0.70710678118654752f));
            g_H[(size_t)m * SEMD + n + 1] = 0.5f * x1 * (1.0f + erff(x1 * 0.70710678118654752f));
        }
}

// ---------------- semantic head GEMM2 + fused MSE reduction ----------------
__global__ void __launch_bounds__(256, 2)
k_gemm2(const float* __restrict__ W2, const float* __restrict__ b2, const float* __restrict__ tgt) {
    extern __shared__ float sm[];
    float* Asm = sm;
    float* Bs  = sm + 256 * APAD;
    int tid = threadIdx.x, tx = tid & 15, ty = tid >> 4;
    int m0 = blockIdx.x * 64, n0 = blockIdx.y * 64;

    const float4* Ag = reinterpret_cast<const float4*>(g_H + (size_t)m0 * SEMD);
    #pragma unroll
    for (int i = 0; i < 16; i++) {
        int f = tid + 256 * i;
        int tok = f >> 6, seg = f & 63;
        float4 v = Ag[tok * 64 + seg];
        int db = seg * 4;
        Asm[(db + 0) * APAD + tok] = v.x;
        Asm[(db + 1) * APAD + tok] = v.y;
        Asm[(db + 2) * APAD + tok] = v.z;
        Asm[(db + 3) * APAD + tok] = v.w;
    }
    __syncthreads();

    unsigned long long acc[4][2];
    #pragma unroll
    for (int r = 0; r < 4; r++) { acc[r][0] = 0ull; acc[r][1] = 0ull; }

    for (int dc = 0; dc < 16; dc++) {
        int dk = tid >> 4, nseg = tid & 15;
        float4 v = *reinterpret_cast<const float4*>(&W2[(size_t)(dc * 16 + dk) * W2VD + n0 + nseg * 4]);
        *reinterpret_cast<float4*>(&Bs[dk * APAD + nseg * 4]) = v;
        __syncthreads();
        #pragma unroll
        for (int kk = 0; kk < 16; kk++) {
            float4 av = *reinterpret_cast<const float4*>(&Asm[(dc * 16 + kk) * APAD + ty * 4]);
            ulonglong2 bb = *reinterpret_cast<const ulonglong2*>(&Bs[kk * APAD + tx * 4]);
            float a[4] = {av.x, av.y, av.z, av.w};
            #pragma unroll
            for (int r = 0; r < 4; r++) {
                unsigned long long a2 = dup2(a[r]);
                fma2(acc[r][0], a2, bb.x);
                fma2(acc[r][1], a2, bb.y);
            }
        }
        __syncthreads();
    }

    float ls = 0.f;
    #pragma unroll
    for (int r = 0; r < 4; r++)
        #pragma unroll
        for (int q = 0; q < 2; q++) {
            int m = m0 + ty * 4 + r, n = n0 + tx * 4 + q * 2;
            float lo, hi;
            unpk(lo, hi, acc[r][q]);
            float p0 = lo + __ldg(&b2[n]);
            float p1 = hi + __ldg(&b2[n + 1]);
            float d0 = p0 - __ldg(&tgt[(size_t)m * W2VD + n]);
            float d1 = p1 - __ldg(&tgt[(size_t)m * W2VD + n + 1]);
            ls += d0 * d0;
            ls += d1 * d1;
        }
    __shared__ float red[8];
    int lane = tid & 31, w = tid >> 5;
    #pragma unroll
    for (int off = 16; off; off >>= 1) ls += __shfl_xor_sync(0xffffffffu, ls, off);
    if (!lane) red[w] = ls;
    __syncthreads();
    if (tid < 8) {
        float t = red[tid];
        #pragma unroll
        for (int off = 4; off; off >>= 1) t += __shfl_xor_sync(0xffu, t, off);
        if (tid == 0) atomicAdd(&g_semsum, t);
    }
}

// ---------------- finalize scalars ----------------
__global__ void k_fin(float* __restrict__ out) {
    if (threadIdx.x == 0) {
        float vq = 0.f;
        #pragma unroll
        for (int i = 0; i < NCB; i++) {
            float m = g_vqp[i] * (1.0f / 4194304.0f);   // mean over B*T*D
            vq += m + 0.25f * m;                         // embedding + COMMIT*commitment
        }
        out[VQ_OFF] = vq;
        out[SEM_OFF] = g_semsum * (1.0f / 16777216.0f);  // mean over B*T*W2V
    }
}

// ---------------- launch ----------------
extern "C" void kernel_launch(void* const* d_in, const int* in_sizes, int n_in,
                              void* d_out, int out_size) {
    const float* z   = (const float*)d_in[0];
    const float* w2v = (const float*)d_in[1];
    const float* E   = (const float*)d_in[2];
    const float* W1  = (const float*)d_in[3];
    const float* b1  = (const float*)d_in[4];
    const float* W2  = (const float*)d_in[5];
    const float* b2  = (const float*)d_in[6];
    float* out = (float*)d_out;

    const int ARG_SMEM  = (256 * APAD + 2 * 16 * BPAD + 64 + KCB) * 4;  // 111,872 B
    const int GEMM_SMEM = (256 * APAD + 16 * APAD) * 4;                 // 73,984 B
    cudaFuncSetAttribute(k_rvq,   cudaFuncAttributeMaxDynamicSharedMemorySize, ARG_SMEM);
    cudaFuncSetAttribute(k_gemm1, cudaFuncAttributeMaxDynamicSharedMemorySize, GEMM_SMEM);
    cudaFuncSetAttribute(k_gemm2, cudaFuncAttributeMaxDynamicSharedMemorySize, GEMM_SMEM);

    k_trans<<<dim3(KCB / 64, DD / 64, NCB), 256>>>(E);
    k_enorm<<<(NCB * KCB * 32 + 255) / 256, 256>>>(E);
    k_init<<<(ZQ_ELEMS + 1023) / 1024, 1024>>>(out);

    k_rvq<<<296, 256, ARG_SMEM>>>(z, E, out);

    k_gemm1<<<dim3(BT / 64, SEMD / 64), 256, GEMM_SMEM>>>(W1, b1);
    k_gemm2<<<dim3(BT / 64, W2VD / 64), 256, GEMM_SMEM>>>(W2, b2, w2v);
    k_fin<<<1, 32>>>(out);
}